// round 6
// baseline (speedup 1.0000x reference)
#include <cuda_runtime.h>
#include <cstdint>

#define NH   12
#define DHD  64
#define NSEQ 1024
#define DM   768
#define NTB  16
#define NS   16384   // NTB * NSEQ tokens

// ---------------------------------------------------------------------------
// Scratch (static device globals; no runtime allocation allowed)
// ---------------------------------------------------------------------------
__device__ __align__(256) float g_q[(size_t)NTB * NH * NSEQ * DHD];   // tf32(0.125*q)
__device__ __align__(256) float g_k[(size_t)NTB * NH * NSEQ * DHD];   // tf32(k)
__device__ __align__(256) float g_v[(size_t)NTB * NH * NSEQ * DHD];   // tf32(v)
__device__ __align__(256) float g_ctx[(size_t)NS * DM];               // tf32(ctx)
__device__ __align__(256) float g_xc[(size_t)NS * DM];                // tf32(x)
__device__ __align__(256) float g_wqc[(size_t)DM * DM];
__device__ __align__(256) float g_wkc[(size_t)DM * DM];
__device__ __align__(256) float g_wvc[(size_t)DM * DM];
__device__ __align__(256) float g_woc[(size_t)DM * DM];

// ---------------------------------------------------------------------------
// Helpers
// ---------------------------------------------------------------------------
__device__ __forceinline__ float f2tf(float x) {
    unsigned u;
    asm("cvt.rna.tf32.f32 %0, %1;" : "=r"(u) : "f"(x));
    return __uint_as_float(u);
}

__device__ __forceinline__ uint32_t smem_u32(const void* p) {
    uint32_t a;
    asm("{ .reg .u64 t; cvta.to.shared.u64 t, %1; cvt.u32.u64 %0, t; }" : "=r"(a) : "l"(p));
    return a;
}

__device__ __forceinline__ void cp16(uint32_t dst, const void* src) {
    asm volatile("cp.async.cg.shared.global [%0], [%1], 16;" :: "r"(dst), "l"(src) : "memory");
}
#define CP_COMMIT() asm volatile("cp.async.commit_group;" ::: "memory")
#define CP_WAIT(n)  asm volatile("cp.async.wait_group %0;" :: "n"(n) : "memory")

__device__ __forceinline__ void mma8(float& c0, float& c1, float& c2, float& c3,
                                     unsigned a0, unsigned a1, unsigned a2, unsigned a3,
                                     unsigned b0, unsigned b1) {
    asm volatile(
        "mma.sync.aligned.m16n8k8.row.col.f32.tf32.tf32.f32 "
        "{%0,%1,%2,%3},{%4,%5,%6,%7},{%8,%9},{%0,%1,%2,%3};"
        : "+f"(c0), "+f"(c1), "+f"(c2), "+f"(c3)
        : "r"(a0), "r"(a1), "r"(a2), "r"(a3), "r"(b0), "r"(b1));
}

// ---------------------------------------------------------------------------
// Fused tf32 pre-round: one launch covers x + the 4 weight matrices
// ---------------------------------------------------------------------------
#define NX4 ((NS * DM) / 4)
#define NW4 ((DM * DM) / 4)
#define NCVT4 (NX4 + 4 * NW4)

__global__ __launch_bounds__(256) void cvt_all_k(const float* __restrict__ x,
                                                 const float* __restrict__ Wq,
                                                 const float* __restrict__ Wk,
                                                 const float* __restrict__ Wv,
                                                 const float* __restrict__ Wo) {
    int i = blockIdx.x * blockDim.x + threadIdx.x;
    if (i >= NCVT4) return;
    const float* s;
    float* d;
    int j;
    if (i < NX4) { s = x; d = g_xc; j = i; }
    else {
        j = i - NX4;
        const int w = j / NW4;
        j -= w * NW4;
        s = (w == 0) ? Wq : (w == 1) ? Wk : (w == 2) ? Wv : Wo;
        d = (w == 0) ? g_wqc : (w == 1) ? g_wkc : (w == 2) ? g_wvc : g_woc;
    }
    float4 v = reinterpret_cast<const float4*>(s)[j];
    v.x = f2tf(v.x); v.y = f2tf(v.y); v.z = f2tf(v.z); v.w = f2tf(v.w);
    reinterpret_cast<float4*>(d)[j] = v;
}

// ---------------------------------------------------------------------------
// HMMA tf32 GEMM: out[s,c] = sum_k A[s,k]*W[c,k] + bias[c]
// CTA 128x128, BK=32, 2-stage cp.async, ONE sync per iteration
// (order: wait -> sync -> prefetch(next) -> compute; the barrier itself is the
//  WAR guard, so the trailing sync is gone).  256 thr (8 warps 4m x 2n).
// mode: 0 = head-split q (scale 0.125 + tf32 round), 1 = head-split k/v, 2 = flat
// ---------------------------------------------------------------------------
#define GSTG 4608                 // floats per array (128*36)
#define GSMEM_F (2 * 2 * GSTG)    // 18432 floats = 73728 B
#define GKIT (DM / 32)            // 24

__device__ __forceinline__ void gemm_body(const float* __restrict__ A,
                                          const float* __restrict__ W,
                                          const float* __restrict__ bias,
                                          float* __restrict__ dst, int mode) {
    extern __shared__ float sm[];
    const uint32_t smb = smem_u32(sm);
    const int tid  = threadIdx.x;
    const int lane = tid & 31, wid = tid >> 5;
    const int wm = (wid & 3) * 32;
    const int wn = (wid >> 2) * 64;
    const int row0 = blockIdx.x * 128, col0 = blockIdx.y * 128;
    const int lr = lane >> 2, lc = lane & 3;

    float acc[2][8][4];
#pragma unroll
    for (int i = 0; i < 2; i++)
#pragma unroll
        for (int j = 0; j < 8; j++)
#pragma unroll
            for (int e = 0; e < 4; e++) acc[i][j][e] = 0.f;

    auto prefetch = [&](int s, int kk) {
        const uint32_t ab = smb + (uint32_t)(s * 2 * GSTG) * 4u;
        const uint32_t bb = ab + (uint32_t)GSTG * 4u;
#pragma unroll
        for (int u = tid; u < 1024; u += 256) {
            const int row = u >> 3, c = (u & 7) << 2;
            cp16(ab + (uint32_t)(row * 36 + c) * 4u,
                 A + (size_t)(row0 + row) * DM + kk + c);
        }
#pragma unroll
        for (int u = tid; u < 1024; u += 256) {
            const int row = u >> 3, c = (u & 7) << 2;
            cp16(bb + (uint32_t)(row * 36 + c) * 4u,
                 W + (size_t)(col0 + row) * DM + kk + c);
        }
    };

    prefetch(0, 0);
    CP_COMMIT();

    for (int it = 0; it < GKIT; it++) {
        const int s = it & 1;
        CP_WAIT(0);
        __syncthreads();
        if (it + 1 < GKIT) {
            prefetch(s ^ 1, (it + 1) * 32);
            CP_COMMIT();
        }

        const float* Asp = sm + s * 2 * GSTG;
        const float* Bsp = Asp + GSTG;
#pragma unroll
        for (int ks = 0; ks < 4; ks++) {
            const int k0 = ks * 8;
            unsigned af[2][4];
#pragma unroll
            for (int mi = 0; mi < 2; mi++) {
                const int r = wm + mi * 16 + lr;
                af[mi][0] = __float_as_uint(Asp[r * 36 + k0 + lc]);
                af[mi][1] = __float_as_uint(Asp[(r + 8) * 36 + k0 + lc]);
                af[mi][2] = __float_as_uint(Asp[r * 36 + k0 + 4 + lc]);
                af[mi][3] = __float_as_uint(Asp[(r + 8) * 36 + k0 + 4 + lc]);
            }
            unsigned bf[8][2];
#pragma unroll
            for (int ni = 0; ni < 8; ni++) {
                const int r = wn + ni * 8 + lr;
                bf[ni][0] = __float_as_uint(Bsp[r * 36 + k0 + lc]);
                bf[ni][1] = __float_as_uint(Bsp[r * 36 + k0 + 4 + lc]);
            }
#pragma unroll
            for (int mi = 0; mi < 2; mi++)
#pragma unroll
                for (int ni = 0; ni < 8; ni++)
                    mma8(acc[mi][ni][0], acc[mi][ni][1], acc[mi][ni][2], acc[mi][ni][3],
                         af[mi][0], af[mi][1], af[mi][2], af[mi][3],
                         bf[ni][0], bf[ni][1]);
        }
    }

    // epilogue
#pragma unroll
    for (int mi = 0; mi < 2; mi++)
#pragma unroll
        for (int ni = 0; ni < 8; ni++)
#pragma unroll
            for (int e = 0; e < 4; e++) {
                const int gr = row0 + wm + mi * 16 + lr + ((e >> 1) << 3);
                const int gc = col0 + wn + ni * 8 + (lc << 1) + (e & 1);
                float v = acc[mi][ni][e] + __ldg(bias + gc);
                if (mode == 0) v = f2tf(v * 0.125f);
                else if (mode == 1) v = f2tf(v);
                if (mode <= 1) {
                    const int tb = gr >> 10, n = gr & 1023;
                    const int h = gc >> 6, d = gc & 63;
                    dst[(((size_t)(tb * NH + h)) * NSEQ + n) * DHD + d] = v;
                } else {
                    dst[(size_t)gr * DM + gc] = v;
                }
            }
}

__global__ __launch_bounds__(256) void gemm_qkv_k(const float* __restrict__ bq,
                                                  const float* __restrict__ bk,
                                                  const float* __restrict__ bv) {
    const int z = blockIdx.z;
    const float* W = (z == 0) ? g_wqc : (z == 1) ? g_wkc : g_wvc;
    const float* b = (z == 0) ? bq : (z == 1) ? bk : bv;
    float* dst = (z == 0) ? g_q : (z == 1) ? g_k : g_v;
    gemm_body(g_xc, W, b, dst, (z == 0) ? 0 : 1);
}

__global__ __launch_bounds__(256) void gemm_out_k(const float* __restrict__ bo,
                                                  float* __restrict__ out) {
    gemm_body(g_ctx, g_woc, bo, out, 2);
}

// ---------------------------------------------------------------------------
// Attention: per (tb,h), 1024x1024x64.
// CTA = 256 q-rows, 256 threads (8 warps x 32 q-rows), KV block = 64 keys,
// 2-stage cp.async with ONE sync per iteration (16 iterations).
// P = relu(q_s k^T); ctx = (P @ v) / (rowsum(P) + eps).
// ---------------------------------------------------------------------------
#define AKV    64
#define QS_STR 68
#define KS_STR 68
#define VS_STR 72   // 72 % 32 == 8 -> conflict-free V B-frag loads
#define PS_STR 68
#define AQ_F   (256 * QS_STR)            // 17408
#define AK_F   (AKV * KS_STR)            // 4352
#define AV_F   (AKV * VS_STR)            // 4608
#define AP_F   (8 * 32 * PS_STR)         // 17408
#define ATT_SMEM_F (AQ_F + 2 * (AK_F + AV_F) + AP_F)   // 52736 floats = 210944 B
#define AKIT (NSEQ / AKV)                // 16

__global__ __launch_bounds__(256) void attn_k() {
    extern __shared__ float sm[];
    float* Qs  = sm;
    float* Ks0 = Qs + AQ_F;                  // [2][64][68]
    float* Vs0 = Ks0 + 2 * AK_F;             // [2][64][72]
    float* Ps  = Vs0 + 2 * AV_F;             // [8][32][68]
    const uint32_t smb = smem_u32(sm);

    const int tid = threadIdx.x, lane = tid & 31, wid = tid >> 5;
    const int lr = lane >> 2, lc = lane & 3;
    const int qb = blockIdx.x, tbh = blockIdx.y;
    const float* qp = g_q + (size_t)tbh * NSEQ * DHD + (size_t)qb * 256 * DHD;
    const float* kp = g_k + (size_t)tbh * NSEQ * DHD;
    const float* vp = g_v + (size_t)tbh * NSEQ * DHD;

    // prefetch KV stage: 1024 chunks K + 1024 chunks V, 256 threads -> 4+4 each
    auto prefetch_kv = [&](int s, int kvb) {
        const uint32_t kb = smb + (uint32_t)(AQ_F + s * AK_F) * 4u;
        const uint32_t vb = smb + (uint32_t)(AQ_F + 2 * AK_F + s * AV_F) * 4u;
        const float* kg = kp + (size_t)kvb * AKV * DHD;
        const float* vg = vp + (size_t)kvb * AKV * DHD;
#pragma unroll
        for (int u = tid; u < 1024; u += 256) {
            const int row = u >> 4, c = (u & 15) << 2;
            cp16(kb + (uint32_t)(row * KS_STR + c) * 4u, kg + row * DHD + c);
        }
#pragma unroll
        for (int u = tid; u < 1024; u += 256) {
            const int row = u >> 4, c = (u & 15) << 2;
            cp16(vb + (uint32_t)(row * VS_STR + c) * 4u, vg + row * DHD + c);
        }
    };

    // Q load (once, 256x64) + first KV stage, one commit group
#pragma unroll
    for (int u = tid; u < 4096; u += 256) {
        const int row = u >> 4, c = (u & 15) << 2;
        cp16(smb + (uint32_t)(row * QS_STR + c) * 4u, qp + row * DHD + c);
    }
    prefetch_kv(0, 0);
    CP_COMMIT();

    float ctx[2][8][4];
#pragma unroll
    for (int i = 0; i < 2; i++)
#pragma unroll
        for (int j = 0; j < 8; j++)
#pragma unroll
            for (int e = 0; e < 4; e++) ctx[i][j][e] = 0.f;
    float rs[2][2] = {{0.f, 0.f}, {0.f, 0.f}};

    const int wm = wid * 32;
    float* Pw = Ps + wid * 32 * PS_STR;

    for (int kvb = 0; kvb < AKIT; kvb++) {
        const int s = kvb & 1;
        CP_WAIT(0);
        __syncthreads();
        if (kvb + 1 < AKIT) {
            prefetch_kv(s ^ 1, kvb + 1);
            CP_COMMIT();
        }

        const float* Ksp = Ks0 + s * AK_F;
        const float* Vsp = Vs0 + s * AV_F;

        // S = q_s @ k^T (warp: 32 q-rows x 64 keys)
        float sacc[2][8][4];
#pragma unroll
        for (int i = 0; i < 2; i++)
#pragma unroll
            for (int j = 0; j < 8; j++)
#pragma unroll
                for (int e = 0; e < 4; e++) sacc[i][j][e] = 0.f;

#pragma unroll
        for (int ks = 0; ks < 8; ks++) {
            const int k0 = ks * 8;
            unsigned af[2][4];
#pragma unroll
            for (int mi = 0; mi < 2; mi++) {
                const int r = wm + mi * 16 + lr;
                af[mi][0] = __float_as_uint(Qs[r * QS_STR + k0 + lc]);
                af[mi][1] = __float_as_uint(Qs[(r + 8) * QS_STR + k0 + lc]);
                af[mi][2] = __float_as_uint(Qs[r * QS_STR + k0 + 4 + lc]);
                af[mi][3] = __float_as_uint(Qs[(r + 8) * QS_STR + k0 + 4 + lc]);
            }
            unsigned bf[8][2];
#pragma unroll
            for (int ni = 0; ni < 8; ni++) {
                const int r = ni * 8 + lr;
                bf[ni][0] = __float_as_uint(Ksp[r * KS_STR + k0 + lc]);
                bf[ni][1] = __float_as_uint(Ksp[r * KS_STR + k0 + 4 + lc]);
            }
#pragma unroll
            for (int mi = 0; mi < 2; mi++)
#pragma unroll
                for (int ni = 0; ni < 8; ni++)
                    mma8(sacc[mi][ni][0], sacc[mi][ni][1], sacc[mi][ni][2], sacc[mi][ni][3],
                         af[mi][0], af[mi][1], af[mi][2], af[mi][3],
                         bf[ni][0], bf[ni][1]);
        }

        // relu + rowsum + stage P (per-warp region, 32x64)
#pragma unroll
        for (int mi = 0; mi < 2; mi++)
#pragma unroll
            for (int ni = 0; ni < 8; ni++) {
                float p0 = fmaxf(sacc[mi][ni][0], 0.f);
                float p1 = fmaxf(sacc[mi][ni][1], 0.f);
                float p2 = fmaxf(sacc[mi][ni][2], 0.f);
                float p3 = fmaxf(sacc[mi][ni][3], 0.f);
                rs[mi][0] += p0 + p1;
                rs[mi][1] += p2 + p3;
                const int rb = mi * 16 + lr;
                const int cb = ni * 8 + (lc << 1);
                *reinterpret_cast<float2*>(Pw + rb * PS_STR + cb)       = make_float2(f2tf(p0), f2tf(p1));
                *reinterpret_cast<float2*>(Pw + (rb + 8) * PS_STR + cb) = make_float2(f2tf(p2), f2tf(p3));
            }
        __syncwarp();

        // ctx += P @ V  (k dim = 64 keys)
#pragma unroll
        for (int ks = 0; ks < 8; ks++) {
            const int k0 = ks * 8;
            unsigned af[2][4];
#pragma unroll
            for (int mi = 0; mi < 2; mi++) {
                const int r = mi * 16 + lr;
                af[mi][0] = __float_as_uint(Pw[r * PS_STR + k0 + lc]);
                af[mi][1] = __float_as_uint(Pw[(r + 8) * PS_STR + k0 + lc]);
                af[mi][2] = __float_as_uint(Pw[r * PS_STR + k0 + 4 + lc]);
                af[mi][3] = __float_as_uint(Pw[(r + 8) * PS_STR + k0 + 4 + lc]);
            }
            unsigned bf[8][2];
#pragma unroll
            for (int ni = 0; ni < 8; ni++) {
                bf[ni][0] = __float_as_uint(Vsp[(k0 + lc) * VS_STR + ni * 8 + lr]);
                bf[ni][1] = __float_as_uint(Vsp[(k0 + 4 + lc) * VS_STR + ni * 8 + lr]);
            }
#pragma unroll
            for (int mi = 0; mi < 2; mi++)
#pragma unroll
                for (int ni = 0; ni < 8; ni++)
                    mma8(ctx[mi][ni][0], ctx[mi][ni][1], ctx[mi][ni][2], ctx[mi][ni][3],
                         af[mi][0], af[mi][1], af[mi][2], af[mi][3],
                         bf[ni][0], bf[ni][1]);
        }
    }

    // finalize rowsums (reduce across the 4 lanes sharing a row)
    float inv[2][2];
#pragma unroll
    for (int mi = 0; mi < 2; mi++)
#pragma unroll
        for (int hh = 0; hh < 2; hh++) {
            float r = rs[mi][hh];
            r += __shfl_xor_sync(0xffffffffu, r, 1);
            r += __shfl_xor_sync(0xffffffffu, r, 2);
            inv[mi][hh] = 1.f / (r + 1e-6f);
        }

    // write merged ctx [s, h*64 + d] (tf32-rounded: feeds out-proj GEMM)
    const int tb = tbh / NH, h = tbh % NH;
#pragma unroll
    for (int mi = 0; mi < 2; mi++)
#pragma unroll
        for (int ni = 0; ni < 8; ni++)
#pragma unroll
            for (int eh = 0; eh < 2; eh++) {
                const int qrow = qb * 256 + wm + mi * 16 + lr + (eh << 3);
                const int sidx = tb * NSEQ + qrow;
                const int c = h * DHD + ni * 8 + (lc << 1);
                const float iv = inv[mi][eh];
                *reinterpret_cast<float2*>(&g_ctx[(size_t)sidx * DM + c]) =
                    make_float2(f2tf(ctx[mi][ni][eh * 2] * iv),
                                f2tf(ctx[mi][ni][eh * 2 + 1] * iv));
            }
}

// ---------------------------------------------------------------------------
// Launch
// ---------------------------------------------------------------------------
extern "C" void kernel_launch(void* const* d_in, const int* in_sizes, int n_in,
                              void* d_out, int out_size) {
    const float* x  = (const float*)d_in[0];
    const float* Wq = (const float*)d_in[1];
    const float* bq = (const float*)d_in[2];
    const float* Wk = (const float*)d_in[3];
    const float* bk = (const float*)d_in[4];
    const float* Wv = (const float*)d_in[5];
    const float* bv = (const float*)d_in[6];
    const float* Wo = (const float*)d_in[7];
    const float* bo = (const float*)d_in[8];
    float* out = (float*)d_out;

    (void)in_sizes; (void)n_in; (void)out_size;

    cudaFuncSetAttribute(gemm_qkv_k, cudaFuncAttributeMaxDynamicSharedMemorySize,
                         (int)(GSMEM_F * sizeof(float)));
    cudaFuncSetAttribute(gemm_out_k, cudaFuncAttributeMaxDynamicSharedMemorySize,
                         (int)(GSMEM_F * sizeof(float)));
    cudaFuncSetAttribute(attn_k, cudaFuncAttributeMaxDynamicSharedMemorySize,
                         (int)(ATT_SMEM_F * sizeof(float)));

    // fused tf32 pre-round (x + 4 weights, one launch)
    cvt_all_k<<<(NCVT4 + 255) / 256, 256>>>(x, Wq, Wk, Wv, Wo);

    // q/k/v projections
    gemm_qkv_k<<<dim3(NS / 128, DM / 128, 3), 256, GSMEM_F * sizeof(float)>>>(bq, bk, bv);

    // spike attention
    attn_k<<<dim3(NSEQ / 256, NTB * NH), 256, ATT_SMEM_F * sizeof(float)>>>();

    // output projection
    gemm_out_k<<<dim3(NS / 128, DM / 128), 256, GSMEM_F * sizeof(float)>>>(bo, out);
}

// round 8
// speedup vs baseline: 1.0193x; 1.0193x over previous
#include <cuda_runtime.h>
#include <cstdint>

#define NH   12
#define DHD  64
#define NSEQ 1024
#define DM   768
#define NTB  16
#define NS   16384   // NTB * NSEQ tokens

// ---------------------------------------------------------------------------
// Scratch (static device globals; no runtime allocation allowed)
// ---------------------------------------------------------------------------
__device__ __align__(256) float g_q[(size_t)NTB * NH * NSEQ * DHD];   // tf32(0.125*q)
__device__ __align__(256) float g_k[(size_t)NTB * NH * NSEQ * DHD];   // tf32(k)
__device__ __align__(256) float g_v[(size_t)NTB * NH * NSEQ * DHD];   // tf32(v)
__device__ __align__(256) float g_ctx[(size_t)NS * DM];               // tf32(ctx)
__device__ __align__(256) float g_xc[(size_t)NS * DM];                // tf32(x)
__device__ __align__(256) float g_wqc[(size_t)DM * DM];
__device__ __align__(256) float g_wkc[(size_t)DM * DM];
__device__ __align__(256) float g_wvc[(size_t)DM * DM];
__device__ __align__(256) float g_woc[(size_t)DM * DM];

// ---------------------------------------------------------------------------
// Helpers
// ---------------------------------------------------------------------------
__device__ __forceinline__ float f2tf(float x) {
    unsigned u;
    asm("cvt.rna.tf32.f32 %0, %1;" : "=r"(u) : "f"(x));
    return __uint_as_float(u);
}

__device__ __forceinline__ uint32_t smem_u32(const void* p) {
    uint32_t a;
    asm("{ .reg .u64 t; cvta.to.shared.u64 t, %1; cvt.u32.u64 %0, t; }" : "=r"(a) : "l"(p));
    return a;
}

__device__ __forceinline__ void cp16(uint32_t dst, const void* src) {
    asm volatile("cp.async.cg.shared.global [%0], [%1], 16;" :: "r"(dst), "l"(src) : "memory");
}
#define CP_COMMIT() asm volatile("cp.async.commit_group;" ::: "memory")
#define CP_WAIT(n)  asm volatile("cp.async.wait_group %0;" :: "n"(n) : "memory")

__device__ __forceinline__ void mma8(float& c0, float& c1, float& c2, float& c3,
                                     unsigned a0, unsigned a1, unsigned a2, unsigned a3,
                                     unsigned b0, unsigned b1) {
    asm volatile(
        "mma.sync.aligned.m16n8k8.row.col.f32.tf32.tf32.f32 "
        "{%0,%1,%2,%3},{%4,%5,%6,%7},{%8,%9},{%0,%1,%2,%3};"
        : "+f"(c0), "+f"(c1), "+f"(c2), "+f"(c3)
        : "r"(a0), "r"(a1), "r"(a2), "r"(a3), "r"(b0), "r"(b1));
}

// ---------------------------------------------------------------------------
// Fused tf32 pre-round: one launch covers x + the 4 weight matrices
// ---------------------------------------------------------------------------
#define NX4 ((NS * DM) / 4)
#define NW4 ((DM * DM) / 4)
#define NCVT4 (NX4 + 4 * NW4)

__global__ __launch_bounds__(256) void cvt_all_k(const float* __restrict__ x,
                                                 const float* __restrict__ Wq,
                                                 const float* __restrict__ Wk,
                                                 const float* __restrict__ Wv,
                                                 const float* __restrict__ Wo) {
    int i = blockIdx.x * blockDim.x + threadIdx.x;
    if (i >= NCVT4) return;
    const float* s;
    float* d;
    int j;
    if (i < NX4) { s = x; d = g_xc; j = i; }
    else {
        j = i - NX4;
        const int w = j / NW4;
        j -= w * NW4;
        s = (w == 0) ? Wq : (w == 1) ? Wk : (w == 2) ? Wv : Wo;
        d = (w == 0) ? g_wqc : (w == 1) ? g_wkc : (w == 2) ? g_wvc : g_woc;
    }
    float4 v = reinterpret_cast<const float4*>(s)[j];
    v.x = f2tf(v.x); v.y = f2tf(v.y); v.z = f2tf(v.z); v.w = f2tf(v.w);
    reinterpret_cast<float4*>(d)[j] = v;
}

// ---------------------------------------------------------------------------
// HMMA tf32 GEMM: out[s,c] = sum_k A[s,k]*W[c,k] + bias[c]
// CTA 256x128, BK=32, 2-stage cp.async (R5 pipeline structure).
// 256 thr = 8 warps as 4(m) x 2(n); WARP TILE 64x64 -> 1.0 LDS per MMA
// (was 32x64 -> 1.5).  acc[4][8][4]=128 regs, ~185 total, no spill at 256thr.
// mode: 0 = head-split q (scale 0.125 + tf32 round), 1 = head-split k/v, 2 = flat
// ---------------------------------------------------------------------------
#define GBM 256
#define GBN 128
#define GA_F (GBM * 36)                    // 9216
#define GB_F (GBN * 36)                    // 4608
#define GSTG_F (GA_F + GB_F)               // 13824
#define GSMEM_F (2 * GSTG_F)               // 27648 floats = 110592 B
#define GKIT (DM / 32)                     // 24

__device__ __forceinline__ void gemm_body(const float* __restrict__ A,
                                          const float* __restrict__ W,
                                          const float* __restrict__ bias,
                                          float* __restrict__ dst, int mode) {
    extern __shared__ float sm[];
    const uint32_t smb = smem_u32(sm);
    const int tid  = threadIdx.x;
    const int lane = tid & 31, wid = tid >> 5;
    const int wm = (wid & 3) * 64;          // 4 m-warps
    const int wn = (wid >> 2) * 64;         // 2 n-warps
    const int row0 = blockIdx.x * GBM, col0 = blockIdx.y * GBN;
    const int lr = lane >> 2, lc = lane & 3;

    float acc[4][8][4];
#pragma unroll
    for (int i = 0; i < 4; i++)
#pragma unroll
        for (int j = 0; j < 8; j++)
#pragma unroll
            for (int e = 0; e < 4; e++) acc[i][j][e] = 0.f;

    // prefetch: A 2048 chunks (8/thr), B 1024 chunks (4/thr)
    auto prefetch = [&](int s, int kk) {
        const uint32_t ab = smb + (uint32_t)(s * GSTG_F) * 4u;
        const uint32_t bb = ab + (uint32_t)GA_F * 4u;
#pragma unroll
        for (int u = tid; u < 2048; u += 256) {
            const int row = u >> 3, c = (u & 7) << 2;
            cp16(ab + (uint32_t)(row * 36 + c) * 4u,
                 A + (size_t)(row0 + row) * DM + kk + c);
        }
#pragma unroll
        for (int u = tid; u < 1024; u += 256) {
            const int row = u >> 3, c = (u & 7) << 2;
            cp16(bb + (uint32_t)(row * 36 + c) * 4u,
                 W + (size_t)(col0 + row) * DM + kk + c);
        }
    };

    prefetch(0, 0);
    CP_COMMIT();

    for (int it = 0; it < GKIT; it++) {
        const int s = it & 1;
        if (it + 1 < GKIT) {
            prefetch(s ^ 1, (it + 1) * 32);
            CP_COMMIT();
            CP_WAIT(1);
        } else {
            CP_WAIT(0);
        }
        __syncthreads();

        const float* Asp = sm + s * GSTG_F;
        const float* Bsp = Asp + GA_F;
#pragma unroll
        for (int ks = 0; ks < 4; ks++) {
            const int k0 = ks * 8;
            unsigned af[4][4];
#pragma unroll
            for (int mi = 0; mi < 4; mi++) {
                const int r = wm + mi * 16 + lr;
                af[mi][0] = __float_as_uint(Asp[r * 36 + k0 + lc]);
                af[mi][1] = __float_as_uint(Asp[(r + 8) * 36 + k0 + lc]);
                af[mi][2] = __float_as_uint(Asp[r * 36 + k0 + 4 + lc]);
                af[mi][3] = __float_as_uint(Asp[(r + 8) * 36 + k0 + 4 + lc]);
            }
            unsigned bf[8][2];
#pragma unroll
            for (int ni = 0; ni < 8; ni++) {
                const int r = wn + ni * 8 + lr;
                bf[ni][0] = __float_as_uint(Bsp[r * 36 + k0 + lc]);
                bf[ni][1] = __float_as_uint(Bsp[r * 36 + k0 + 4 + lc]);
            }
#pragma unroll
            for (int mi = 0; mi < 4; mi++)
#pragma unroll
                for (int ni = 0; ni < 8; ni++)
                    mma8(acc[mi][ni][0], acc[mi][ni][1], acc[mi][ni][2], acc[mi][ni][3],
                         af[mi][0], af[mi][1], af[mi][2], af[mi][3],
                         bf[ni][0], bf[ni][1]);
        }
        __syncthreads();
    }

    // epilogue
#pragma unroll
    for (int mi = 0; mi < 4; mi++)
#pragma unroll
        for (int ni = 0; ni < 8; ni++)
#pragma unroll
            for (int e = 0; e < 4; e++) {
                const int gr = row0 + wm + mi * 16 + lr + ((e >> 1) << 3);
                const int gc = col0 + wn + ni * 8 + (lc << 1) + (e & 1);
                float v = acc[mi][ni][e] + __ldg(bias + gc);
                if (mode == 0) v = f2tf(v * 0.125f);
                else if (mode == 1) v = f2tf(v);
                if (mode <= 1) {
                    const int tb = gr >> 10, n = gr & 1023;
                    const int h = gc >> 6, d = gc & 63;
                    dst[(((size_t)(tb * NH + h)) * NSEQ + n) * DHD + d] = v;
                } else {
                    dst[(size_t)gr * DM + gc] = v;
                }
            }
}

__global__ __launch_bounds__(256) void gemm_qkv_k(const float* __restrict__ bq,
                                                  const float* __restrict__ bk,
                                                  const float* __restrict__ bv) {
    const int z = blockIdx.z;
    const float* W = (z == 0) ? g_wqc : (z == 1) ? g_wkc : g_wvc;
    const float* b = (z == 0) ? bq : (z == 1) ? bk : bv;
    float* dst = (z == 0) ? g_q : (z == 1) ? g_k : g_v;
    gemm_body(g_xc, W, b, dst, (z == 0) ? 0 : 1);
}

__global__ __launch_bounds__(256) void gemm_out_k(const float* __restrict__ bo,
                                                  float* __restrict__ out) {
    gemm_body(g_ctx, g_woc, bo, out, 2);
}

// ---------------------------------------------------------------------------
// Attention (exact R5 856.8us version): per (tb,h), 1024x1024x64.
// CTA = 128 q-rows, 128 threads, KV block 32, 2-stage cp.async, 2 CTAs/SM.
// P = relu(q_s k^T); ctx = (P @ v) / (rowsum(P) + eps).
// ---------------------------------------------------------------------------
#define QS_STR 68
#define KS_STR 68
#define VS_STR 72   // 72 % 32 == 8 -> conflict-free V B-frag loads
#define PS_STR 36
#define AQ_F   (128 * QS_STR)            // 8704
#define AK_F   (32 * KS_STR)             // 2176
#define AV_F   (32 * VS_STR)             // 2304
#define AP_F   (4 * 32 * PS_STR)         // 4608
#define ATT_SMEM_F (AQ_F + 2 * (AK_F + AV_F) + AP_F)   // 22272 floats = 89088 B

__global__ __launch_bounds__(128, 2) void attn_k() {
    extern __shared__ float sm[];
    float* Qs  = sm;
    float* Ks0 = Qs + AQ_F;                  // [2][32][68]
    float* Vs0 = Ks0 + 2 * AK_F;             // [2][32][72]
    float* Ps  = Vs0 + 2 * AV_F;             // [4][32][36]
    const uint32_t smb = smem_u32(sm);

    const int tid = threadIdx.x, lane = tid & 31, wid = tid >> 5;
    const int lr = lane >> 2, lc = lane & 3;
    const int qb = blockIdx.x, tbh = blockIdx.y;
    const float* qp = g_q + (size_t)tbh * NSEQ * DHD + (size_t)qb * 128 * DHD;
    const float* kp = g_k + (size_t)tbh * NSEQ * DHD;
    const float* vp = g_v + (size_t)tbh * NSEQ * DHD;

    auto prefetch_kv = [&](int s, int kvb) {
        const uint32_t kb = smb + (uint32_t)(AQ_F + s * AK_F) * 4u;
        const uint32_t vb = smb + (uint32_t)(AQ_F + 2 * AK_F + s * AV_F) * 4u;
        const float* kg = kp + (size_t)kvb * 32 * DHD;
        const float* vg = vp + (size_t)kvb * 32 * DHD;
#pragma unroll
        for (int u = tid; u < 512; u += 128) {
            const int row = u >> 4, c = (u & 15) << 2;
            cp16(kb + (uint32_t)(row * KS_STR + c) * 4u, kg + row * DHD + c);
        }
#pragma unroll
        for (int u = tid; u < 512; u += 128) {
            const int row = u >> 4, c = (u & 15) << 2;
            cp16(vb + (uint32_t)(row * VS_STR + c) * 4u, vg + row * DHD + c);
        }
    };

    // Q load (once) + first KV stage, one commit group
#pragma unroll
    for (int u = tid; u < 2048; u += 128) {
        const int row = u >> 4, c = (u & 15) << 2;
        cp16(smb + (uint32_t)(row * QS_STR + c) * 4u, qp + row * DHD + c);
    }
    prefetch_kv(0, 0);
    CP_COMMIT();

    float ctx[2][8][4];
#pragma unroll
    for (int i = 0; i < 2; i++)
#pragma unroll
        for (int j = 0; j < 8; j++)
#pragma unroll
            for (int e = 0; e < 4; e++) ctx[i][j][e] = 0.f;
    float rs[2][2] = {{0.f, 0.f}, {0.f, 0.f}};

    const int wm = wid * 32;
    float* Pw = Ps + wid * 32 * PS_STR;

    for (int kvb = 0; kvb < NSEQ / 32; kvb++) {
        const int s = kvb & 1;
        if (kvb + 1 < NSEQ / 32) {
            prefetch_kv(s ^ 1, kvb + 1);
            CP_COMMIT();
            CP_WAIT(1);
        } else {
            CP_WAIT(0);
        }
        __syncthreads();

        const float* Ksp = Ks0 + s * AK_F;
        const float* Vsp = Vs0 + s * AV_F;

        // S = q_s @ k^T (warp: 32 q-rows x 32 keys)
        float sacc[2][4][4];
#pragma unroll
        for (int i = 0; i < 2; i++)
#pragma unroll
            for (int j = 0; j < 4; j++)
#pragma unroll
                for (int e = 0; e < 4; e++) sacc[i][j][e] = 0.f;

#pragma unroll
        for (int ks = 0; ks < 8; ks++) {
            const int k0 = ks * 8;
            unsigned af[2][4];
#pragma unroll
            for (int mi = 0; mi < 2; mi++) {
                const int r = wm + mi * 16 + lr;
                af[mi][0] = __float_as_uint(Qs[r * QS_STR + k0 + lc]);
                af[mi][1] = __float_as_uint(Qs[(r + 8) * QS_STR + k0 + lc]);
                af[mi][2] = __float_as_uint(Qs[r * QS_STR + k0 + 4 + lc]);
                af[mi][3] = __float_as_uint(Qs[(r + 8) * QS_STR + k0 + 4 + lc]);
            }
            unsigned bf[4][2];
#pragma unroll
            for (int ni = 0; ni < 4; ni++) {
                const int r = ni * 8 + lr;
                bf[ni][0] = __float_as_uint(Ksp[r * KS_STR + k0 + lc]);
                bf[ni][1] = __float_as_uint(Ksp[r * KS_STR + k0 + 4 + lc]);
            }
#pragma unroll
            for (int mi = 0; mi < 2; mi++)
#pragma unroll
                for (int ni = 0; ni < 4; ni++)
                    mma8(sacc[mi][ni][0], sacc[mi][ni][1], sacc[mi][ni][2], sacc[mi][ni][3],
                         af[mi][0], af[mi][1], af[mi][2], af[mi][3],
                         bf[ni][0], bf[ni][1]);
        }

        // relu + rowsum + stage P (per-warp region)
#pragma unroll
        for (int mi = 0; mi < 2; mi++)
#pragma unroll
            for (int ni = 0; ni < 4; ni++) {
                float p0 = fmaxf(sacc[mi][ni][0], 0.f);
                float p1 = fmaxf(sacc[mi][ni][1], 0.f);
                float p2 = fmaxf(sacc[mi][ni][2], 0.f);
                float p3 = fmaxf(sacc[mi][ni][3], 0.f);
                rs[mi][0] += p0 + p1;
                rs[mi][1] += p2 + p3;
                const int rb = mi * 16 + lr;
                const int cb = ni * 8 + (lc << 1);
                *reinterpret_cast<float2*>(Pw + rb * PS_STR + cb)       = make_float2(f2tf(p0), f2tf(p1));
                *reinterpret_cast<float2*>(Pw + (rb + 8) * PS_STR + cb) = make_float2(f2tf(p2), f2tf(p3));
            }
        __syncwarp();

        // ctx += P @ V
#pragma unroll
        for (int ks = 0; ks < 4; ks++) {
            const int k0 = ks * 8;
            unsigned af[2][4];
#pragma unroll
            for (int mi = 0; mi < 2; mi++) {
                const int r = mi * 16 + lr;
                af[mi][0] = __float_as_uint(Pw[r * PS_STR + k0 + lc]);
                af[mi][1] = __float_as_uint(Pw[(r + 8) * PS_STR + k0 + lc]);
                af[mi][2] = __float_as_uint(Pw[r * PS_STR + k0 + 4 + lc]);
                af[mi][3] = __float_as_uint(Pw[(r + 8) * PS_STR + k0 + 4 + lc]);
            }
            unsigned bf[8][2];
#pragma unroll
            for (int ni = 0; ni < 8; ni++) {
                bf[ni][0] = __float_as_uint(Vsp[(k0 + lc) * VS_STR + ni * 8 + lr]);
                bf[ni][1] = __float_as_uint(Vsp[(k0 + 4 + lc) * VS_STR + ni * 8 + lr]);
            }
#pragma unroll
            for (int mi = 0; mi < 2; mi++)
#pragma unroll
                for (int ni = 0; ni < 8; ni++)
                    mma8(ctx[mi][ni][0], ctx[mi][ni][1], ctx[mi][ni][2], ctx[mi][ni][3],
                         af[mi][0], af[mi][1], af[mi][2], af[mi][3],
                         bf[ni][0], bf[ni][1]);
        }
        __syncthreads();
    }

    // finalize rowsums
    float inv[2][2];
#pragma unroll
    for (int mi = 0; mi < 2; mi++)
#pragma unroll
        for (int hh = 0; hh < 2; hh++) {
            float r = rs[mi][hh];
            r += __shfl_xor_sync(0xffffffffu, r, 1);
            r += __shfl_xor_sync(0xffffffffu, r, 2);
            inv[mi][hh] = 1.f / (r + 1e-6f);
        }

    // write merged ctx [s, h*64 + d] (tf32-rounded: feeds out-proj GEMM)
    const int tb = tbh / NH, h = tbh % NH;
#pragma unroll
    for (int mi = 0; mi < 2; mi++)
#pragma unroll
        for (int ni = 0; ni < 8; ni++)
#pragma unroll
            for (int e = 0; e < 4; e++) {
                const int qrow = qb * 128 + wm + mi * 16 + lr + ((e >> 1) << 3);
                const int s = tb * NSEQ + qrow;
                const int c = h * DHD + ni * 8 + (lc << 1) + (e & 1);
                g_ctx[(size_t)s * DM + c] = f2tf(ctx[mi][ni][e] * inv[mi][e >> 1]);
            }
}

// ---------------------------------------------------------------------------
// Launch
// ---------------------------------------------------------------------------
extern "C" void kernel_launch(void* const* d_in, const int* in_sizes, int n_in,
                              void* d_out, int out_size) {
    const float* x  = (const float*)d_in[0];
    const float* Wq = (const float*)d_in[1];
    const float* bq = (const float*)d_in[2];
    const float* Wk = (const float*)d_in[3];
    const float* bk = (const float*)d_in[4];
    const float* Wv = (const float*)d_in[5];
    const float* bv = (const float*)d_in[6];
    const float* Wo = (const float*)d_in[7];
    const float* bo = (const float*)d_in[8];
    float* out = (float*)d_out;

    (void)in_sizes; (void)n_in; (void)out_size;

    cudaFuncSetAttribute(gemm_qkv_k, cudaFuncAttributeMaxDynamicSharedMemorySize,
                         (int)(GSMEM_F * sizeof(float)));
    cudaFuncSetAttribute(gemm_out_k, cudaFuncAttributeMaxDynamicSharedMemorySize,
                         (int)(GSMEM_F * sizeof(float)));
    cudaFuncSetAttribute(attn_k, cudaFuncAttributeMaxDynamicSharedMemorySize,
                         (int)(ATT_SMEM_F * sizeof(float)));

    // fused tf32 pre-round (x + 4 weights, one launch)
    cvt_all_k<<<(NCVT4 + 255) / 256, 256>>>(x, Wq, Wk, Wv, Wo);

    // q/k/v projections (CTA 256x128, warp 64x64)
    gemm_qkv_k<<<dim3(NS / GBM, DM / GBN, 3), 256, GSMEM_F * sizeof(float)>>>(bq, bk, bv);

    // spike attention (R5 config)
    attn_k<<<dim3(NSEQ / 128, NTB * NH), 128, ATT_SMEM_F * sizeof(float)>>>();

    // output projection
    gemm_out_k<<<dim3(NS / GBM, DM / GBN), 256, GSMEM_F * sizeof(float)>>>(bo, out);
}

// round 9
// speedup vs baseline: 1.0813x; 1.0609x over previous
#include <cuda_runtime.h>
#include <cstdint>

#define NH   12
#define DHD  64
#define NSEQ 1024
#define DM   768
#define NTB  16
#define NS   16384   // NTB * NSEQ tokens

// ---------------------------------------------------------------------------
// Scratch (static device globals; no runtime allocation allowed)
// ---------------------------------------------------------------------------
__device__ __align__(256) float g_q[(size_t)NTB * NH * NSEQ * DHD];   // tf32(0.125*q)
__device__ __align__(256) float g_k[(size_t)NTB * NH * NSEQ * DHD];   // tf32(k)
__device__ __align__(256) float g_v[(size_t)NTB * NH * NSEQ * DHD];   // tf32(v)
__device__ __align__(256) float g_ctx[(size_t)NS * DM];               // tf32(ctx)
__device__ __align__(256) float g_xc[(size_t)NS * DM];                // tf32(x)
__device__ __align__(256) float g_wqc[(size_t)DM * DM];
__device__ __align__(256) float g_wkc[(size_t)DM * DM];
__device__ __align__(256) float g_wvc[(size_t)DM * DM];
__device__ __align__(256) float g_woc[(size_t)DM * DM];

// ---------------------------------------------------------------------------
// Helpers
// ---------------------------------------------------------------------------
__device__ __forceinline__ float f2tf(float x) {
    unsigned u;
    asm("cvt.rna.tf32.f32 %0, %1;" : "=r"(u) : "f"(x));
    return __uint_as_float(u);
}

__device__ __forceinline__ uint32_t smem_u32(const void* p) {
    uint32_t a;
    asm("{ .reg .u64 t; cvta.to.shared.u64 t, %1; cvt.u32.u64 %0, t; }" : "=r"(a) : "l"(p));
    return a;
}

__device__ __forceinline__ void cp16(uint32_t dst, const void* src) {
    asm volatile("cp.async.cg.shared.global [%0], [%1], 16;" :: "r"(dst), "l"(src) : "memory");
}
#define CP_COMMIT() asm volatile("cp.async.commit_group;" ::: "memory")
#define CP_WAIT(n)  asm volatile("cp.async.wait_group %0;" :: "n"(n) : "memory")

__device__ __forceinline__ void mma8(float& c0, float& c1, float& c2, float& c3,
                                     unsigned a0, unsigned a1, unsigned a2, unsigned a3,
                                     unsigned b0, unsigned b1) {
    asm volatile(
        "mma.sync.aligned.m16n8k8.row.col.f32.tf32.tf32.f32 "
        "{%0,%1,%2,%3},{%4,%5,%6,%7},{%8,%9},{%0,%1,%2,%3};"
        : "+f"(c0), "+f"(c1), "+f"(c2), "+f"(c3)
        : "r"(a0), "r"(a1), "r"(a2), "r"(a3), "r"(b0), "r"(b1));
}

// ---------------------------------------------------------------------------
// Fused tf32 pre-round: one launch covers x + the 4 weight matrices
// ---------------------------------------------------------------------------
#define NX4 ((NS * DM) / 4)
#define NW4 ((DM * DM) / 4)
#define NCVT4 (NX4 + 4 * NW4)

__global__ __launch_bounds__(256) void cvt_all_k(const float* __restrict__ x,
                                                 const float* __restrict__ Wq,
                                                 const float* __restrict__ Wk,
                                                 const float* __restrict__ Wv,
                                                 const float* __restrict__ Wo) {
    int i = blockIdx.x * blockDim.x + threadIdx.x;
    if (i >= NCVT4) return;
    const float* s;
    float* d;
    int j;
    if (i < NX4) { s = x; d = g_xc; j = i; }
    else {
        j = i - NX4;
        const int w = j / NW4;
        j -= w * NW4;
        s = (w == 0) ? Wq : (w == 1) ? Wk : (w == 2) ? Wv : Wo;
        d = (w == 0) ? g_wqc : (w == 1) ? g_wkc : (w == 2) ? g_wvc : g_woc;
    }
    float4 v = reinterpret_cast<const float4*>(s)[j];
    v.x = f2tf(v.x); v.y = f2tf(v.y); v.z = f2tf(v.z); v.w = f2tf(v.w);
    reinterpret_cast<float4*>(d)[j] = v;
}

// ---------------------------------------------------------------------------
// HMMA tf32 GEMM: out[s,c] = sum_k A[s,k]*W[c,k] + bias[c]
// CTA 128x128, 128 threads = 4 warps as 2(m) x 2(n), WARP TILE 64x64
// (1.0 LDS per MMA).  BK=32, 2-stage cp.async, ONE sync per iteration.
// 128-thr CTA keeps reg file use at ~29K -> 2 CTAs/SM: same 8 warps/SM as the
// R8 256-thr config but as two independent schedulable streams (R6 lesson).
// mode: 0 = head-split q (scale 0.125 + tf32 round), 1 = head-split k/v, 2 = flat
// ---------------------------------------------------------------------------
#define GBM 128
#define GBN 128
#define GA_F (GBM * 36)                    // 4608
#define GB_F (GBN * 36)                    // 4608
#define GSTG_F (GA_F + GB_F)               // 9216
#define GSMEM_F (2 * GSTG_F)               // 18432 floats = 73728 B
#define GKIT (DM / 32)                     // 24

__device__ __forceinline__ void gemm_body(const float* __restrict__ A,
                                          const float* __restrict__ W,
                                          const float* __restrict__ bias,
                                          float* __restrict__ dst, int mode) {
    extern __shared__ float sm[];
    const uint32_t smb = smem_u32(sm);
    const int tid  = threadIdx.x;
    const int lane = tid & 31, wid = tid >> 5;
    const int wm = (wid & 1) * 64;          // 2 m-warps
    const int wn = (wid >> 1) * 64;         // 2 n-warps
    const int row0 = blockIdx.x * GBM, col0 = blockIdx.y * GBN;
    const int lr = lane >> 2, lc = lane & 3;

    float acc[4][8][4];
#pragma unroll
    for (int i = 0; i < 4; i++)
#pragma unroll
        for (int j = 0; j < 8; j++)
#pragma unroll
            for (int e = 0; e < 4; e++) acc[i][j][e] = 0.f;

    // prefetch: A 1024 + B 1024 chunks of 16B, 128 threads -> 8+8 each
    auto prefetch = [&](int s, int kk) {
        const uint32_t ab = smb + (uint32_t)(s * GSTG_F) * 4u;
        const uint32_t bb = ab + (uint32_t)GA_F * 4u;
#pragma unroll
        for (int u = tid; u < 1024; u += 128) {
            const int row = u >> 3, c = (u & 7) << 2;
            cp16(ab + (uint32_t)(row * 36 + c) * 4u,
                 A + (size_t)(row0 + row) * DM + kk + c);
        }
#pragma unroll
        for (int u = tid; u < 1024; u += 128) {
            const int row = u >> 3, c = (u & 7) << 2;
            cp16(bb + (uint32_t)(row * 36 + c) * 4u,
                 W + (size_t)(col0 + row) * DM + kk + c);
        }
    };

    prefetch(0, 0);
    CP_COMMIT();

    for (int it = 0; it < GKIT; it++) {
        const int s = it & 1;
        CP_WAIT(0);
        __syncthreads();
        if (it + 1 < GKIT) {
            prefetch(s ^ 1, (it + 1) * 32);
            CP_COMMIT();
        }

        const float* Asp = sm + s * GSTG_F;
        const float* Bsp = Asp + GA_F;
#pragma unroll
        for (int ks = 0; ks < 4; ks++) {
            const int k0 = ks * 8;
            unsigned af[4][4];
#pragma unroll
            for (int mi = 0; mi < 4; mi++) {
                const int r = wm + mi * 16 + lr;
                af[mi][0] = __float_as_uint(Asp[r * 36 + k0 + lc]);
                af[mi][1] = __float_as_uint(Asp[(r + 8) * 36 + k0 + lc]);
                af[mi][2] = __float_as_uint(Asp[r * 36 + k0 + 4 + lc]);
                af[mi][3] = __float_as_uint(Asp[(r + 8) * 36 + k0 + 4 + lc]);
            }
            unsigned bf[8][2];
#pragma unroll
            for (int ni = 0; ni < 8; ni++) {
                const int r = wn + ni * 8 + lr;
                bf[ni][0] = __float_as_uint(Bsp[r * 36 + k0 + lc]);
                bf[ni][1] = __float_as_uint(Bsp[r * 36 + k0 + 4 + lc]);
            }
#pragma unroll
            for (int mi = 0; mi < 4; mi++)
#pragma unroll
                for (int ni = 0; ni < 8; ni++)
                    mma8(acc[mi][ni][0], acc[mi][ni][1], acc[mi][ni][2], acc[mi][ni][3],
                         af[mi][0], af[mi][1], af[mi][2], af[mi][3],
                         bf[ni][0], bf[ni][1]);
        }
    }

    // epilogue
#pragma unroll
    for (int mi = 0; mi < 4; mi++)
#pragma unroll
        for (int ni = 0; ni < 8; ni++)
#pragma unroll
            for (int e = 0; e < 4; e++) {
                const int gr = row0 + wm + mi * 16 + lr + ((e >> 1) << 3);
                const int gc = col0 + wn + ni * 8 + (lc << 1) + (e & 1);
                float v = acc[mi][ni][e] + __ldg(bias + gc);
                if (mode == 0) v = f2tf(v * 0.125f);
                else if (mode == 1) v = f2tf(v);
                if (mode <= 1) {
                    const int tb = gr >> 10, n = gr & 1023;
                    const int h = gc >> 6, d = gc & 63;
                    dst[(((size_t)(tb * NH + h)) * NSEQ + n) * DHD + d] = v;
                } else {
                    dst[(size_t)gr * DM + gc] = v;
                }
            }
}

__global__ __launch_bounds__(128) void gemm_qkv_k(const float* __restrict__ bq,
                                                  const float* __restrict__ bk,
                                                  const float* __restrict__ bv) {
    const int z = blockIdx.z;
    const float* W = (z == 0) ? g_wqc : (z == 1) ? g_wkc : g_wvc;
    const float* b = (z == 0) ? bq : (z == 1) ? bk : bv;
    float* dst = (z == 0) ? g_q : (z == 1) ? g_k : g_v;
    gemm_body(g_xc, W, b, dst, (z == 0) ? 0 : 1);
}

__global__ __launch_bounds__(128) void gemm_out_k(const float* __restrict__ bo,
                                                  float* __restrict__ out) {
    gemm_body(g_ctx, g_woc, bo, out, 2);
}

// ---------------------------------------------------------------------------
// Attention (exact R5 856.8us version): per (tb,h), 1024x1024x64.
// CTA = 128 q-rows, 128 threads, KV block 32, 2-stage cp.async, 2 CTAs/SM.
// P = relu(q_s k^T); ctx = (P @ v) / (rowsum(P) + eps).
// ---------------------------------------------------------------------------
#define QS_STR 68
#define KS_STR 68
#define VS_STR 72   // 72 % 32 == 8 -> conflict-free V B-frag loads
#define PS_STR 36
#define AQ_F   (128 * QS_STR)            // 8704
#define AK_F   (32 * KS_STR)             // 2176
#define AV_F   (32 * VS_STR)             // 2304
#define AP_F   (4 * 32 * PS_STR)         // 4608
#define ATT_SMEM_F (AQ_F + 2 * (AK_F + AV_F) + AP_F)   // 22272 floats = 89088 B

__global__ __launch_bounds__(128, 2) void attn_k() {
    extern __shared__ float sm[];
    float* Qs  = sm;
    float* Ks0 = Qs + AQ_F;                  // [2][32][68]
    float* Vs0 = Ks0 + 2 * AK_F;             // [2][32][72]
    float* Ps  = Vs0 + 2 * AV_F;             // [4][32][36]
    const uint32_t smb = smem_u32(sm);

    const int tid = threadIdx.x, lane = tid & 31, wid = tid >> 5;
    const int lr = lane >> 2, lc = lane & 3;
    const int qb = blockIdx.x, tbh = blockIdx.y;
    const float* qp = g_q + (size_t)tbh * NSEQ * DHD + (size_t)qb * 128 * DHD;
    const float* kp = g_k + (size_t)tbh * NSEQ * DHD;
    const float* vp = g_v + (size_t)tbh * NSEQ * DHD;

    auto prefetch_kv = [&](int s, int kvb) {
        const uint32_t kb = smb + (uint32_t)(AQ_F + s * AK_F) * 4u;
        const uint32_t vb = smb + (uint32_t)(AQ_F + 2 * AK_F + s * AV_F) * 4u;
        const float* kg = kp + (size_t)kvb * 32 * DHD;
        const float* vg = vp + (size_t)kvb * 32 * DHD;
#pragma unroll
        for (int u = tid; u < 512; u += 128) {
            const int row = u >> 4, c = (u & 15) << 2;
            cp16(kb + (uint32_t)(row * KS_STR + c) * 4u, kg + row * DHD + c);
        }
#pragma unroll
        for (int u = tid; u < 512; u += 128) {
            const int row = u >> 4, c = (u & 15) << 2;
            cp16(vb + (uint32_t)(row * VS_STR + c) * 4u, vg + row * DHD + c);
        }
    };

    // Q load (once) + first KV stage, one commit group
#pragma unroll
    for (int u = tid; u < 2048; u += 128) {
        const int row = u >> 4, c = (u & 15) << 2;
        cp16(smb + (uint32_t)(row * QS_STR + c) * 4u, qp + row * DHD + c);
    }
    prefetch_kv(0, 0);
    CP_COMMIT();

    float ctx[2][8][4];
#pragma unroll
    for (int i = 0; i < 2; i++)
#pragma unroll
        for (int j = 0; j < 8; j++)
#pragma unroll
            for (int e = 0; e < 4; e++) ctx[i][j][e] = 0.f;
    float rs[2][2] = {{0.f, 0.f}, {0.f, 0.f}};

    const int wm = wid * 32;
    float* Pw = Ps + wid * 32 * PS_STR;

    for (int kvb = 0; kvb < NSEQ / 32; kvb++) {
        const int s = kvb & 1;
        if (kvb + 1 < NSEQ / 32) {
            prefetch_kv(s ^ 1, kvb + 1);
            CP_COMMIT();
            CP_WAIT(1);
        } else {
            CP_WAIT(0);
        }
        __syncthreads();

        const float* Ksp = Ks0 + s * AK_F;
        const float* Vsp = Vs0 + s * AV_F;

        // S = q_s @ k^T (warp: 32 q-rows x 32 keys)
        float sacc[2][4][4];
#pragma unroll
        for (int i = 0; i < 2; i++)
#pragma unroll
            for (int j = 0; j < 4; j++)
#pragma unroll
                for (int e = 0; e < 4; e++) sacc[i][j][e] = 0.f;

#pragma unroll
        for (int ks = 0; ks < 8; ks++) {
            const int k0 = ks * 8;
            unsigned af[2][4];
#pragma unroll
            for (int mi = 0; mi < 2; mi++) {
                const int r = wm + mi * 16 + lr;
                af[mi][0] = __float_as_uint(Qs[r * QS_STR + k0 + lc]);
                af[mi][1] = __float_as_uint(Qs[(r + 8) * QS_STR + k0 + lc]);
                af[mi][2] = __float_as_uint(Qs[r * QS_STR + k0 + 4 + lc]);
                af[mi][3] = __float_as_uint(Qs[(r + 8) * QS_STR + k0 + 4 + lc]);
            }
            unsigned bf[4][2];
#pragma unroll
            for (int ni = 0; ni < 4; ni++) {
                const int r = ni * 8 + lr;
                bf[ni][0] = __float_as_uint(Ksp[r * KS_STR + k0 + lc]);
                bf[ni][1] = __float_as_uint(Ksp[r * KS_STR + k0 + 4 + lc]);
            }
#pragma unroll
            for (int mi = 0; mi < 2; mi++)
#pragma unroll
                for (int ni = 0; ni < 4; ni++)
                    mma8(sacc[mi][ni][0], sacc[mi][ni][1], sacc[mi][ni][2], sacc[mi][ni][3],
                         af[mi][0], af[mi][1], af[mi][2], af[mi][3],
                         bf[ni][0], bf[ni][1]);
        }

        // relu + rowsum + stage P (per-warp region)
#pragma unroll
        for (int mi = 0; mi < 2; mi++)
#pragma unroll
            for (int ni = 0; ni < 4; ni++) {
                float p0 = fmaxf(sacc[mi][ni][0], 0.f);
                float p1 = fmaxf(sacc[mi][ni][1], 0.f);
                float p2 = fmaxf(sacc[mi][ni][2], 0.f);
                float p3 = fmaxf(sacc[mi][ni][3], 0.f);
                rs[mi][0] += p0 + p1;
                rs[mi][1] += p2 + p3;
                const int rb = mi * 16 + lr;
                const int cb = ni * 8 + (lc << 1);
                *reinterpret_cast<float2*>(Pw + rb * PS_STR + cb)       = make_float2(f2tf(p0), f2tf(p1));
                *reinterpret_cast<float2*>(Pw + (rb + 8) * PS_STR + cb) = make_float2(f2tf(p2), f2tf(p3));
            }
        __syncwarp();

        // ctx += P @ V
#pragma unroll
        for (int ks = 0; ks < 4; ks++) {
            const int k0 = ks * 8;
            unsigned af[2][4];
#pragma unroll
            for (int mi = 0; mi < 2; mi++) {
                const int r = mi * 16 + lr;
                af[mi][0] = __float_as_uint(Pw[r * PS_STR + k0 + lc]);
                af[mi][1] = __float_as_uint(Pw[(r + 8) * PS_STR + k0 + lc]);
                af[mi][2] = __float_as_uint(Pw[r * PS_STR + k0 + 4 + lc]);
                af[mi][3] = __float_as_uint(Pw[(r + 8) * PS_STR + k0 + 4 + lc]);
            }
            unsigned bf[8][2];
#pragma unroll
            for (int ni = 0; ni < 8; ni++) {
                bf[ni][0] = __float_as_uint(Vsp[(k0 + lc) * VS_STR + ni * 8 + lr]);
                bf[ni][1] = __float_as_uint(Vsp[(k0 + 4 + lc) * VS_STR + ni * 8 + lr]);
            }
#pragma unroll
            for (int mi = 0; mi < 2; mi++)
#pragma unroll
                for (int ni = 0; ni < 8; ni++)
                    mma8(ctx[mi][ni][0], ctx[mi][ni][1], ctx[mi][ni][2], ctx[mi][ni][3],
                         af[mi][0], af[mi][1], af[mi][2], af[mi][3],
                         bf[ni][0], bf[ni][1]);
        }
        __syncthreads();
    }

    // finalize rowsums
    float inv[2][2];
#pragma unroll
    for (int mi = 0; mi < 2; mi++)
#pragma unroll
        for (int hh = 0; hh < 2; hh++) {
            float r = rs[mi][hh];
            r += __shfl_xor_sync(0xffffffffu, r, 1);
            r += __shfl_xor_sync(0xffffffffu, r, 2);
            inv[mi][hh] = 1.f / (r + 1e-6f);
        }

    // write merged ctx [s, h*64 + d] (tf32-rounded: feeds out-proj GEMM)
    const int tb = tbh / NH, h = tbh % NH;
#pragma unroll
    for (int mi = 0; mi < 2; mi++)
#pragma unroll
        for (int ni = 0; ni < 8; ni++)
#pragma unroll
            for (int e = 0; e < 4; e++) {
                const int qrow = qb * 128 + wm + mi * 16 + lr + ((e >> 1) << 3);
                const int s = tb * NSEQ + qrow;
                const int c = h * DHD + ni * 8 + (lc << 1) + (e & 1);
                g_ctx[(size_t)s * DM + c] = f2tf(ctx[mi][ni][e] * inv[mi][e >> 1]);
            }
}

// ---------------------------------------------------------------------------
// Launch
// ---------------------------------------------------------------------------
extern "C" void kernel_launch(void* const* d_in, const int* in_sizes, int n_in,
                              void* d_out, int out_size) {
    const float* x  = (const float*)d_in[0];
    const float* Wq = (const float*)d_in[1];
    const float* bq = (const float*)d_in[2];
    const float* Wk = (const float*)d_in[3];
    const float* bk = (const float*)d_in[4];
    const float* Wv = (const float*)d_in[5];
    const float* bv = (const float*)d_in[6];
    const float* Wo = (const float*)d_in[7];
    const float* bo = (const float*)d_in[8];
    float* out = (float*)d_out;

    (void)in_sizes; (void)n_in; (void)out_size;

    cudaFuncSetAttribute(gemm_qkv_k, cudaFuncAttributeMaxDynamicSharedMemorySize,
                         (int)(GSMEM_F * sizeof(float)));
    cudaFuncSetAttribute(gemm_out_k, cudaFuncAttributeMaxDynamicSharedMemorySize,
                         (int)(GSMEM_F * sizeof(float)));
    cudaFuncSetAttribute(attn_k, cudaFuncAttributeMaxDynamicSharedMemorySize,
                         (int)(ATT_SMEM_F * sizeof(float)));

    // fused tf32 pre-round (x + 4 weights, one launch)
    cvt_all_k<<<(NCVT4 + 255) / 256, 256>>>(x, Wq, Wk, Wv, Wo);

    // q/k/v projections (CTA 128x128, 4 warps of 64x64, 2 CTAs/SM)
    gemm_qkv_k<<<dim3(NS / GBM, DM / GBN, 3), 128, GSMEM_F * sizeof(float)>>>(bq, bk, bv);

    // spike attention (R5 config)
    attn_k<<<dim3(NSEQ / 128, NTB * NH), 128, ATT_SMEM_F * sizeof(float)>>>();

    // output projection
    gemm_out_k<<<dim3(NS / GBM, DM / GBN), 128, GSMEM_F * sizeof(float)>>>(bo, out);
}

// round 13
// speedup vs baseline: 2.0445x; 1.8908x over previous
#include <cuda_runtime.h>
#include <cuda_fp16.h>
#include <cstdint>

#define NH   12
#define DHD  64
#define NSEQ 1024
#define DM   768
#define NTB  16
#define NS   16384   // NTB * NSEQ tokens

// ---------------------------------------------------------------------------
// Scratch (static device globals; no runtime allocation allowed)
// ---------------------------------------------------------------------------
__device__ __align__(256) __half g_q[(size_t)NTB * NH * NSEQ * DHD];   // h(0.125*q)
__device__ __align__(256) __half g_k[(size_t)NTB * NH * NSEQ * DHD];   // h(k)
__device__ __align__(256) __half g_v[(size_t)NTB * NH * NSEQ * DHD];   // h(v)
__device__ __align__(256) __half g_ctx[(size_t)NS * DM];               // h(ctx)
__device__ __align__(256) __half g_xc[(size_t)NS * DM];                // h(x)
__device__ __align__(256) __half g_wqc[(size_t)DM * DM];
__device__ __align__(256) __half g_wkc[(size_t)DM * DM];
__device__ __align__(256) __half g_wvc[(size_t)DM * DM];
__device__ __align__(256) __half g_woc[(size_t)DM * DM];

// ---------------------------------------------------------------------------
// Helpers
// ---------------------------------------------------------------------------
__device__ __forceinline__ uint32_t smem_u32(const void* p) {
    uint32_t a;
    asm("{ .reg .u64 t; cvta.to.shared.u64 t, %1; cvt.u32.u64 %0, t; }" : "=r"(a) : "l"(p));
    return a;
}

__device__ __forceinline__ void cp16(uint32_t dst, const void* src) {
    asm volatile("cp.async.cg.shared.global [%0], [%1], 16;" :: "r"(dst), "l"(src) : "memory");
}
#define CP_COMMIT() asm volatile("cp.async.commit_group;" ::: "memory")
#define CP_WAIT(n)  asm volatile("cp.async.wait_group %0;" :: "n"(n) : "memory")

__device__ __forceinline__ unsigned ldh2(const __half* p) {
    return *reinterpret_cast<const unsigned*>(p);
}

// fp16 MMA, fp32 accumulate: D(16x8) += A(16x16) * B(16x8)
__device__ __forceinline__ void mma16(float& c0, float& c1, float& c2, float& c3,
                                      unsigned a0, unsigned a1, unsigned a2, unsigned a3,
                                      unsigned b0, unsigned b1) {
    asm volatile(
        "mma.sync.aligned.m16n8k16.row.col.f32.f16.f16.f32 "
        "{%0,%1,%2,%3},{%4,%5,%6,%7},{%8,%9},{%0,%1,%2,%3};"
        : "+f"(c0), "+f"(c1), "+f"(c2), "+f"(c3)
        : "r"(a0), "r"(a1), "r"(a2), "r"(a3), "r"(b0), "r"(b1));
}

// ldmatrix x4 transposed b16 (for V: keys-major smem -> B-frag of k=keys)
__device__ __forceinline__ void ldmx4t(unsigned& r0, unsigned& r1, unsigned& r2, unsigned& r3,
                                       uint32_t addr) {
    asm volatile("ldmatrix.sync.aligned.m8n8.x4.trans.shared.b16 {%0,%1,%2,%3}, [%4];"
                 : "=r"(r0), "=r"(r1), "=r"(r2), "=r"(r3) : "r"(addr));
}

// ---------------------------------------------------------------------------
// Fused fp16 pre-convert: one launch covers x + the 4 weight matrices
// ---------------------------------------------------------------------------
#define NX4 ((NS * DM) / 4)
#define NW4 ((DM * DM) / 4)
#define NCVT4 (NX4 + 4 * NW4)

__global__ __launch_bounds__(256) void cvt_all_k(const float* __restrict__ x,
                                                 const float* __restrict__ Wq,
                                                 const float* __restrict__ Wk,
                                                 const float* __restrict__ Wv,
                                                 const float* __restrict__ Wo) {
    int i = blockIdx.x * blockDim.x + threadIdx.x;
    if (i >= NCVT4) return;
    const float* s;
    __half* d;
    int j;
    if (i < NX4) { s = x; d = g_xc; j = i; }
    else {
        j = i - NX4;
        const int w = j / NW4;
        j -= w * NW4;
        s = (w == 0) ? Wq : (w == 1) ? Wk : (w == 2) ? Wv : Wo;
        d = (w == 0) ? g_wqc : (w == 1) ? g_wkc : (w == 2) ? g_wvc : g_woc;
    }
    float4 v = reinterpret_cast<const float4*>(s)[j];
    __half2 h0 = __floats2half2_rn(v.x, v.y);
    __half2 h1 = __floats2half2_rn(v.z, v.w);
    uint2 pk;
    pk.x = *reinterpret_cast<unsigned*>(&h0);
    pk.y = *reinterpret_cast<unsigned*>(&h1);
    reinterpret_cast<uint2*>(d)[j] = pk;
}

// ---------------------------------------------------------------------------
// fp16 HMMA GEMM: out[s,c] = sum_k A[s,k]*W[c,k] + bias[c]
// CTA 128x128, 128 thr = 4 warps (2m x 2n), warp tile 64x64, BK=64 halves,
// 2-stage cp.async, one sync per iteration.  Smem rows padded to 72 halves
// (144 B: 16B-aligned for cp.async, bank-rotation conflict-free).
// mode: 0 = head-split q (x0.125), 1 = head-split k/v, 2 = flat fp32 out
// ---------------------------------------------------------------------------
#define GBM 128
#define GBN 128
#define GSTR 72
#define GA_H (GBM * GSTR)                   // 9216 halves
#define GSTG_H (2 * GA_H)                   // 18432 halves (A + B)
#define GSMEM_B (2 * GSTG_H * 2)            // 73728 bytes
#define GKIT (DM / 64)                      // 12

__device__ __forceinline__ void gemm_body(const __half* __restrict__ A,
                                          const __half* __restrict__ W,
                                          const float* __restrict__ bias,
                                          void* __restrict__ dstp, int mode) {
    extern __shared__ __half smh[];
    const uint32_t smb = smem_u32(smh);
    const int tid  = threadIdx.x;
    const int lane = tid & 31, wid = tid >> 5;
    const int wm = (wid & 1) * 64;
    const int wn = (wid >> 1) * 64;
    const int row0 = blockIdx.x * GBM, col0 = blockIdx.y * GBN;
    const int lr = lane >> 2, lc = lane & 3;

    float acc[4][8][4];
#pragma unroll
    for (int i = 0; i < 4; i++)
#pragma unroll
        for (int j = 0; j < 8; j++)
#pragma unroll
            for (int e = 0; e < 4; e++) acc[i][j][e] = 0.f;

    // prefetch one stage: A 1024 + B 1024 chunks of 16B (8 halves), 8+8/thr
    auto prefetch = [&](int s, int kk) {
        const uint32_t ab = smb + (uint32_t)(s * GSTG_H) * 2u;
        const uint32_t bb = ab + (uint32_t)GA_H * 2u;
#pragma unroll
        for (int u = tid; u < 1024; u += 128) {
            const int row = u >> 3, c = (u & 7) << 3;
            cp16(ab + (uint32_t)(row * GSTR + c) * 2u,
                 A + (size_t)(row0 + row) * DM + kk + c);
        }
#pragma unroll
        for (int u = tid; u < 1024; u += 128) {
            const int row = u >> 3, c = (u & 7) << 3;
            cp16(bb + (uint32_t)(row * GSTR + c) * 2u,
                 W + (size_t)(col0 + row) * DM + kk + c);
        }
    };

    prefetch(0, 0);
    CP_COMMIT();

    for (int it = 0; it < GKIT; it++) {
        const int s = it & 1;
        CP_WAIT(0);
        __syncthreads();
        if (it + 1 < GKIT) {
            prefetch(s ^ 1, (it + 1) * 64);
            CP_COMMIT();
        }

        const __half* Asp = smh + s * GSTG_H;
        const __half* Bsp = Asp + GA_H;
#pragma unroll
        for (int ks = 0; ks < 4; ks++) {
            const int kb = ks * 16;
            unsigned af[4][4];
#pragma unroll
            for (int mi = 0; mi < 4; mi++) {
                const int r = wm + mi * 16 + lr;
                af[mi][0] = ldh2(Asp + r * GSTR + kb + 2 * lc);
                af[mi][1] = ldh2(Asp + (r + 8) * GSTR + kb + 2 * lc);
                af[mi][2] = ldh2(Asp + r * GSTR + kb + 2 * lc + 8);
                af[mi][3] = ldh2(Asp + (r + 8) * GSTR + kb + 2 * lc + 8);
            }
            unsigned bf[8][2];
#pragma unroll
            for (int ni = 0; ni < 8; ni++) {
                const int r = wn + ni * 8 + lr;
                bf[ni][0] = ldh2(Bsp + r * GSTR + kb + 2 * lc);
                bf[ni][1] = ldh2(Bsp + r * GSTR + kb + 2 * lc + 8);
            }
#pragma unroll
            for (int mi = 0; mi < 4; mi++)
#pragma unroll
                for (int ni = 0; ni < 8; ni++)
                    mma16(acc[mi][ni][0], acc[mi][ni][1], acc[mi][ni][2], acc[mi][ni][3],
                          af[mi][0], af[mi][1], af[mi][2], af[mi][3],
                          bf[ni][0], bf[ni][1]);
        }
    }

    // epilogue
#pragma unroll
    for (int mi = 0; mi < 4; mi++)
#pragma unroll
        for (int ni = 0; ni < 8; ni++)
#pragma unroll
            for (int eh = 0; eh < 2; eh++) {
                const int gr = row0 + wm + mi * 16 + lr + (eh << 3);
                const int gc = col0 + wn + ni * 8 + (lc << 1);
                float v0 = acc[mi][ni][eh * 2]     + __ldg(bias + gc);
                float v1 = acc[mi][ni][eh * 2 + 1] + __ldg(bias + gc + 1);
                if (mode == 2) {
                    float* dst = (float*)dstp;
                    *reinterpret_cast<float2*>(dst + (size_t)gr * DM + gc) =
                        make_float2(v0, v1);
                } else {
                    if (mode == 0) { v0 *= 0.125f; v1 *= 0.125f; }
                    __half* dst = (__half*)dstp;
                    const int tb = gr >> 10, n = gr & 1023;
                    const int h = gc >> 6, d = gc & 63;
                    __half2 hv = __floats2half2_rn(v0, v1);
                    *reinterpret_cast<__half2*>(
                        dst + (((size_t)(tb * NH + h)) * NSEQ + n) * DHD + d) = hv;
                }
            }
}

__global__ __launch_bounds__(128) void gemm_qkv_k(const float* __restrict__ bq,
                                                  const float* __restrict__ bk,
                                                  const float* __restrict__ bv) {
    const int z = blockIdx.z;
    const __half* W = (z == 0) ? g_wqc : (z == 1) ? g_wkc : g_wvc;
    const float* b = (z == 0) ? bq : (z == 1) ? bk : bv;
    __half* dst = (z == 0) ? g_q : (z == 1) ? g_k : g_v;
    gemm_body(g_xc, W, b, dst, (z == 0) ? 0 : 1);
}

__global__ __launch_bounds__(128) void gemm_out_k(const float* __restrict__ bo,
                                                  float* __restrict__ out) {
    gemm_body(g_ctx, g_woc, bo, out, 2);
}

// ---------------------------------------------------------------------------
// Attention (fp16): per (tb,h), 1024x1024x64. CTA = 128 q-rows, 128 threads,
// KV block 32, 2-stage cp.async, 2 CTAs/SM.  S = q_s k^T (k16 x 4);
// P staged fp16; ctx += P V via ldmatrix.x4.trans B-frags (k16 x 2).
// ---------------------------------------------------------------------------
#define ASTR 72                      // Q/K/V row stride in halves (144 B)
#define PSTR 40                      // P row stride in halves (80 B)
#define AQ_H   (128 * ASTR)          // 9216
#define AK_H   (32 * ASTR)           // 2304
#define AV_H   (32 * ASTR)           // 2304
#define AP_H   (4 * 32 * PSTR)       // 5120
#define ATT_SMEM_B ((AQ_H + 2 * AK_H + 2 * AV_H + AP_H) * 2)   // 47104 B

__global__ __launch_bounds__(128, 2) void attn_k() {
    extern __shared__ __half smh[];
    __half* Qs  = smh;
    __half* Ks0 = Qs + AQ_H;                 // [2][32][72]
    __half* Vs0 = Ks0 + 2 * AK_H;            // [2][32][72]
    __half* Ps  = Vs0 + 2 * AV_H;            // [4][32][40]
    const uint32_t smb = smem_u32(smh);

    const int tid = threadIdx.x, lane = tid & 31, wid = tid >> 5;
    const int lr = lane >> 2, lc = lane & 3;
    const int qb = blockIdx.x, tbh = blockIdx.y;
    const __half* qp = g_q + (size_t)tbh * NSEQ * DHD + (size_t)qb * 128 * DHD;
    const __half* kp = g_k + (size_t)tbh * NSEQ * DHD;
    const __half* vp = g_v + (size_t)tbh * NSEQ * DHD;

    // prefetch KV stage: K 256 + V 256 chunks of 16B, 2+2 per thread
    auto prefetch_kv = [&](int s, int kvb) {
        const uint32_t kb = smb + (uint32_t)(AQ_H + s * AK_H) * 2u;
        const uint32_t vb = smb + (uint32_t)(AQ_H + 2 * AK_H + s * AV_H) * 2u;
        const __half* kg = kp + (size_t)kvb * 32 * DHD;
        const __half* vg = vp + (size_t)kvb * 32 * DHD;
#pragma unroll
        for (int u = tid; u < 256; u += 128) {
            const int row = u >> 3, c = (u & 7) << 3;
            cp16(kb + (uint32_t)(row * ASTR + c) * 2u, kg + row * DHD + c);
        }
#pragma unroll
        for (int u = tid; u < 256; u += 128) {
            const int row = u >> 3, c = (u & 7) << 3;
            cp16(vb + (uint32_t)(row * ASTR + c) * 2u, vg + row * DHD + c);
        }
    };

    // Q load (once, 128x64 halves = 1024 chunks) + first KV stage
#pragma unroll
    for (int u = tid; u < 1024; u += 128) {
        const int row = u >> 3, c = (u & 7) << 3;
        cp16(smb + (uint32_t)(row * ASTR + c) * 2u, qp + row * DHD + c);
    }
    prefetch_kv(0, 0);
    CP_COMMIT();

    float ctx[2][8][4];
#pragma unroll
    for (int i = 0; i < 2; i++)
#pragma unroll
        for (int j = 0; j < 8; j++)
#pragma unroll
            for (int e = 0; e < 4; e++) ctx[i][j][e] = 0.f;
    float rs[2][2] = {{0.f, 0.f}, {0.f, 0.f}};

    const int wm = wid * 32;
    __half* Pw = Ps + wid * 32 * PSTR;
    const uint32_t vstage_u32[2] = {
        smb + (uint32_t)(AQ_H + 2 * AK_H) * 2u,
        smb + (uint32_t)(AQ_H + 2 * AK_H + AV_H) * 2u
    };

    for (int kvb = 0; kvb < NSEQ / 32; kvb++) {
        const int s = kvb & 1;
        if (kvb + 1 < NSEQ / 32) {
            prefetch_kv(s ^ 1, kvb + 1);
            CP_COMMIT();
            CP_WAIT(1);
        } else {
            CP_WAIT(0);
        }
        __syncthreads();

        const __half* Ksp = Ks0 + s * AK_H;

        // S = q_s @ k^T (warp: 32 q-rows x 32 keys), k-dim = dh 64 = 4 x k16
        float sacc[2][4][4];
#pragma unroll
        for (int i = 0; i < 2; i++)
#pragma unroll
            for (int j = 0; j < 4; j++)
#pragma unroll
                for (int e = 0; e < 4; e++) sacc[i][j][e] = 0.f;

#pragma unroll
        for (int ks = 0; ks < 4; ks++) {
            const int kb = ks * 16;
            unsigned af[2][4];
#pragma unroll
            for (int mi = 0; mi < 2; mi++) {
                const int r = wm + mi * 16 + lr;
                af[mi][0] = ldh2(Qs + r * ASTR + kb + 2 * lc);
                af[mi][1] = ldh2(Qs + (r + 8) * ASTR + kb + 2 * lc);
                af[mi][2] = ldh2(Qs + r * ASTR + kb + 2 * lc + 8);
                af[mi][3] = ldh2(Qs + (r + 8) * ASTR + kb + 2 * lc + 8);
            }
            unsigned bf[4][2];
#pragma unroll
            for (int ni = 0; ni < 4; ni++) {
                const int r = ni * 8 + lr;
                bf[ni][0] = ldh2(Ksp + r * ASTR + kb + 2 * lc);
                bf[ni][1] = ldh2(Ksp + r * ASTR + kb + 2 * lc + 8);
            }
#pragma unroll
            for (int mi = 0; mi < 2; mi++)
#pragma unroll
                for (int ni = 0; ni < 4; ni++)
                    mma16(sacc[mi][ni][0], sacc[mi][ni][1], sacc[mi][ni][2], sacc[mi][ni][3],
                          af[mi][0], af[mi][1], af[mi][2], af[mi][3],
                          bf[ni][0], bf[ni][1]);
        }

        // relu + rowsum + stage P as fp16 (per-warp region, 32x32)
#pragma unroll
        for (int mi = 0; mi < 2; mi++)
#pragma unroll
            for (int ni = 0; ni < 4; ni++) {
                float p0 = fmaxf(sacc[mi][ni][0], 0.f);
                float p1 = fmaxf(sacc[mi][ni][1], 0.f);
                float p2 = fmaxf(sacc[mi][ni][2], 0.f);
                float p3 = fmaxf(sacc[mi][ni][3], 0.f);
                rs[mi][0] += p0 + p1;
                rs[mi][1] += p2 + p3;
                const int rb = mi * 16 + lr;
                const int cb = ni * 8 + (lc << 1);
                *reinterpret_cast<__half2*>(Pw + rb * PSTR + cb) =
                    __floats2half2_rn(p0, p1);
                *reinterpret_cast<__half2*>(Pw + (rb + 8) * PSTR + cb) =
                    __floats2half2_rn(p2, p3);
            }
        __syncwarp();

        // ctx += P @ V ; k-dim = 32 keys = 2 x k16, V B-frags via ldmatrix.trans
#pragma unroll
        for (int ks = 0; ks < 2; ks++) {
            const int kb = ks * 16;
            unsigned af[2][4];
#pragma unroll
            for (int mi = 0; mi < 2; mi++) {
                const int r = mi * 16 + lr;
                af[mi][0] = ldh2(Pw + r * PSTR + kb + 2 * lc);
                af[mi][1] = ldh2(Pw + (r + 8) * PSTR + kb + 2 * lc);
                af[mi][2] = ldh2(Pw + r * PSTR + kb + 2 * lc + 8);
                af[mi][3] = ldh2(Pw + (r + 8) * PSTR + kb + 2 * lc + 8);
            }
            unsigned bf[8][2];
            const int vkey = kb + (lane & 15);
            const int vcol8 = (lane >> 4) << 3;
#pragma unroll
            for (int ni2 = 0; ni2 < 4; ni2++) {
                const uint32_t addr = vstage_u32[s] +
                    (uint32_t)(vkey * ASTR + ni2 * 16 + vcol8) * 2u;
                ldmx4t(bf[2 * ni2][0], bf[2 * ni2][1],
                       bf[2 * ni2 + 1][0], bf[2 * ni2 + 1][1], addr);
            }
#pragma unroll
            for (int mi = 0; mi < 2; mi++)
#pragma unroll
                for (int ni = 0; ni < 8; ni++)
                    mma16(ctx[mi][ni][0], ctx[mi][ni][1], ctx[mi][ni][2], ctx[mi][ni][3],
                          af[mi][0], af[mi][1], af[mi][2], af[mi][3],
                          bf[ni][0], bf[ni][1]);
        }
        __syncthreads();
    }

    // finalize rowsums (reduce across the 4 lanes sharing a row)
    float inv[2][2];
#pragma unroll
    for (int mi = 0; mi < 2; mi++)
#pragma unroll
        for (int hh = 0; hh < 2; hh++) {
            float r = rs[mi][hh];
            r += __shfl_xor_sync(0xffffffffu, r, 1);
            r += __shfl_xor_sync(0xffffffffu, r, 2);
            inv[mi][hh] = 1.f / (r + 1e-6f);
        }

    // write merged ctx [s, h*64+d] as fp16 (feeds out-proj GEMM)
    const int tb = tbh / NH, h = tbh % NH;
#pragma unroll
    for (int mi = 0; mi < 2; mi++)
#pragma unroll
        for (int ni = 0; ni < 8; ni++)
#pragma unroll
            for (int eh = 0; eh < 2; eh++) {
                const int qrow = qb * 128 + wm + mi * 16 + lr + (eh << 3);
                const int sidx = tb * NSEQ + qrow;
                const int c = h * DHD + ni * 8 + (lc << 1);
                const float iv = inv[mi][eh];
                *reinterpret_cast<__half2*>(&g_ctx[(size_t)sidx * DM + c]) =
                    __floats2half2_rn(ctx[mi][ni][eh * 2] * iv,
                                      ctx[mi][ni][eh * 2 + 1] * iv);
            }
}

// ---------------------------------------------------------------------------
// Launch
// ---------------------------------------------------------------------------
extern "C" void kernel_launch(void* const* d_in, const int* in_sizes, int n_in,
                              void* d_out, int out_size) {
    const float* x  = (const float*)d_in[0];
    const float* Wq = (const float*)d_in[1];
    const float* bq = (const float*)d_in[2];
    const float* Wk = (const float*)d_in[3];
    const float* bk = (const float*)d_in[4];
    const float* Wv = (const float*)d_in[5];
    const float* bv = (const float*)d_in[6];
    const float* Wo = (const float*)d_in[7];
    const float* bo = (const float*)d_in[8];
    float* out = (float*)d_out;

    (void)in_sizes; (void)n_in; (void)out_size;

    cudaFuncSetAttribute(gemm_qkv_k, cudaFuncAttributeMaxDynamicSharedMemorySize, GSMEM_B);
    cudaFuncSetAttribute(gemm_out_k, cudaFuncAttributeMaxDynamicSharedMemorySize, GSMEM_B);
    cudaFuncSetAttribute(attn_k, cudaFuncAttributeMaxDynamicSharedMemorySize, ATT_SMEM_B);

    // fused fp16 pre-convert (x + 4 weights, one launch)
    cvt_all_k<<<(NCVT4 + 255) / 256, 256>>>(x, Wq, Wk, Wv, Wo);

    // q/k/v projections (CTA 128x128, 4 warps of 64x64)
    gemm_qkv_k<<<dim3(NS / GBM, DM / GBN, 3), 128, GSMEM_B>>>(bq, bk, bv);

    // spike attention
    attn_k<<<dim3(NSEQ / 128, NTB * NH), 128, ATT_SMEM_B>>>();

    // output projection
    gemm_out_k<<<dim3(NS / GBM, DM / GBN), 128, GSMEM_B>>>(bo, out);
}

// round 15
// speedup vs baseline: 2.2941x; 1.1221x over previous
#include <cuda_runtime.h>
#include <cuda_fp16.h>
#include <cstdint>

#define NH   12
#define DHD  64
#define NSEQ 1024
#define DM   768
#define NTB  16
#define NS   16384   // NTB * NSEQ tokens

// ---------------------------------------------------------------------------
// Scratch (static device globals; no runtime allocation allowed)
// ---------------------------------------------------------------------------
__device__ __align__(256) __half g_q[(size_t)NTB * NH * NSEQ * DHD];   // h(0.125*q)
__device__ __align__(256) __half g_k[(size_t)NTB * NH * NSEQ * DHD];   // h(k)
__device__ __align__(256) __half g_v[(size_t)NTB * NH * NSEQ * DHD];   // h(v)
__device__ __align__(256) __half g_ctx[(size_t)NS * DM];               // h(ctx)
__device__ __align__(256) __half g_xc[(size_t)NS * DM];                // h(x)
__device__ __align__(256) __half g_wqc[(size_t)DM * DM];
__device__ __align__(256) __half g_wkc[(size_t)DM * DM];
__device__ __align__(256) __half g_wvc[(size_t)DM * DM];
__device__ __align__(256) __half g_woc[(size_t)DM * DM];

// ---------------------------------------------------------------------------
// Helpers
// ---------------------------------------------------------------------------
__device__ __forceinline__ uint32_t smem_u32(const void* p) {
    uint32_t a;
    asm("{ .reg .u64 t; cvta.to.shared.u64 t, %1; cvt.u32.u64 %0, t; }" : "=r"(a) : "l"(p));
    return a;
}

__device__ __forceinline__ void cp16(uint32_t dst, const void* src) {
    asm volatile("cp.async.cg.shared.global [%0], [%1], 16;" :: "r"(dst), "l"(src) : "memory");
}
#define CP_COMMIT() asm volatile("cp.async.commit_group;" ::: "memory")
#define CP_WAIT(n)  asm volatile("cp.async.wait_group %0;" :: "n"(n) : "memory")

// fp16 MMA, fp32 accumulate: D(16x8) += A(16x16) * B(16x8)
__device__ __forceinline__ void mma16(float& c0, float& c1, float& c2, float& c3,
                                      unsigned a0, unsigned a1, unsigned a2, unsigned a3,
                                      unsigned b0, unsigned b1) {
    asm volatile(
        "mma.sync.aligned.m16n8k16.row.col.f32.f16.f16.f32 "
        "{%0,%1,%2,%3},{%4,%5,%6,%7},{%8,%9},{%0,%1,%2,%3};"
        : "+f"(c0), "+f"(c1), "+f"(c2), "+f"(c3)
        : "r"(a0), "r"(a1), "r"(a2), "r"(a3), "r"(b0), "r"(b1));
}

// ldmatrix x4 (non-trans / trans) b16
__device__ __forceinline__ void ldmx4(unsigned& r0, unsigned& r1, unsigned& r2, unsigned& r3,
                                      uint32_t addr) {
    asm volatile("ldmatrix.sync.aligned.m8n8.x4.shared.b16 {%0,%1,%2,%3}, [%4];"
                 : "=r"(r0), "=r"(r1), "=r"(r2), "=r"(r3) : "r"(addr));
}
__device__ __forceinline__ void ldmx4t(unsigned& r0, unsigned& r1, unsigned& r2, unsigned& r3,
                                       uint32_t addr) {
    asm volatile("ldmatrix.sync.aligned.m8n8.x4.trans.shared.b16 {%0,%1,%2,%3}, [%4];"
                 : "=r"(r0), "=r"(r1), "=r"(r2), "=r"(r3) : "r"(addr));
}

__device__ __forceinline__ unsigned packh2(float a, float b) {
    __half2 h = __floats2half2_rn(a, b);
    return *reinterpret_cast<unsigned*>(&h);
}

// ---------------------------------------------------------------------------
// Fused fp16 pre-convert: one launch covers x + the 4 weight matrices
// ---------------------------------------------------------------------------
#define NX4 ((NS * DM) / 4)
#define NW4 ((DM * DM) / 4)
#define NCVT4 (NX4 + 4 * NW4)

__global__ __launch_bounds__(256) void cvt_all_k(const float* __restrict__ x,
                                                 const float* __restrict__ Wq,
                                                 const float* __restrict__ Wk,
                                                 const float* __restrict__ Wv,
                                                 const float* __restrict__ Wo) {
    int i = blockIdx.x * blockDim.x + threadIdx.x;
    if (i >= NCVT4) return;
    const float* s;
    __half* d;
    int j;
    if (i < NX4) { s = x; d = g_xc; j = i; }
    else {
        j = i - NX4;
        const int w = j / NW4;
        j -= w * NW4;
        s = (w == 0) ? Wq : (w == 1) ? Wk : (w == 2) ? Wv : Wo;
        d = (w == 0) ? g_wqc : (w == 1) ? g_wkc : (w == 2) ? g_wvc : g_woc;
    }
    float4 v = reinterpret_cast<const float4*>(s)[j];
    __half2 h0 = __floats2half2_rn(v.x, v.y);
    __half2 h1 = __floats2half2_rn(v.z, v.w);
    uint2 pk;
    pk.x = *reinterpret_cast<unsigned*>(&h0);
    pk.y = *reinterpret_cast<unsigned*>(&h1);
    reinterpret_cast<uint2*>(d)[j] = pk;
}

// ---------------------------------------------------------------------------
// fp16 HMMA GEMM: out[s,c] = sum_k A[s,k]*W[c,k] + bias[c]
// CTA 128x128, 128 thr = 4 warps (2m x 2n), warp tile 64x64, BK=64 halves,
// 2-stage cp.async, one sync/iter.  ALL fragments via ldmatrix.x4
// (8 ldmatrix + 32 mma per k16-step instead of 32 LDS.32 + 32 mma).
// Row stride 72 halves = 144B: 16B-aligned, 4-bank rotation/row ->
// ldmatrix conflict-free.
// mode: 0 = head-split q (x0.125), 1 = head-split k/v, 2 = flat fp32 out
// ---------------------------------------------------------------------------
#define GBM 128
#define GBN 128
#define GSTR 72
#define GA_H (GBM * GSTR)                   // 9216 halves
#define GSTG_H (2 * GA_H)                   // 18432 halves (A + B)
#define GSMEM_B (2 * GSTG_H * 2)            // 73728 bytes
#define GKIT (DM / 64)                      // 12

__device__ __forceinline__ void gemm_body(const __half* __restrict__ A,
                                          const __half* __restrict__ W,
                                          const float* __restrict__ bias,
                                          void* __restrict__ dstp, int mode) {
    extern __shared__ __half smh[];
    const uint32_t smb = smem_u32(smh);
    const int tid  = threadIdx.x;
    const int lane = tid & 31, wid = tid >> 5;
    const int wm = (wid & 1) * 64;
    const int wn = (wid >> 1) * 64;
    const int row0 = blockIdx.x * GBM, col0 = blockIdx.y * GBN;
    const int lr = lane >> 2, lc = lane & 3;

    // ldmatrix lane-address components
    const int m8 = lane >> 3, rr = lane & 7;
    const int a_row = ((m8 & 1) << 3) + rr;   // A: row offset, col += ((m8>>1)<<3)
    const int a_col = (m8 >> 1) << 3;
    const int b_row = ((m8 >> 1) << 3) + rr;  // B: n-row offset, col += ((m8&1)<<3)
    const int b_col = (m8 & 1) << 3;

    float acc[4][8][4];
#pragma unroll
    for (int i = 0; i < 4; i++)
#pragma unroll
        for (int j = 0; j < 8; j++)
#pragma unroll
            for (int e = 0; e < 4; e++) acc[i][j][e] = 0.f;

    // prefetch one stage: A 1024 + B 1024 chunks of 16B (8 halves), 8+8/thr
    auto prefetch = [&](int s, int kk) {
        const uint32_t ab = smb + (uint32_t)(s * GSTG_H) * 2u;
        const uint32_t bb = ab + (uint32_t)GA_H * 2u;
#pragma unroll
        for (int u = tid; u < 1024; u += 128) {
            const int row = u >> 3, c = (u & 7) << 3;
            cp16(ab + (uint32_t)(row * GSTR + c) * 2u,
                 A + (size_t)(row0 + row) * DM + kk + c);
        }
#pragma unroll
        for (int u = tid; u < 1024; u += 128) {
            const int row = u >> 3, c = (u & 7) << 3;
            cp16(bb + (uint32_t)(row * GSTR + c) * 2u,
                 W + (size_t)(col0 + row) * DM + kk + c);
        }
    };

    prefetch(0, 0);
    CP_COMMIT();

    for (int it = 0; it < GKIT; it++) {
        const int s = it & 1;
        CP_WAIT(0);
        __syncthreads();
        if (it + 1 < GKIT) {
            prefetch(s ^ 1, (it + 1) * 64);
            CP_COMMIT();
        }

        const uint32_t abase = smb + (uint32_t)(s * GSTG_H) * 2u;
        const uint32_t bbase = abase + (uint32_t)GA_H * 2u;
#pragma unroll
        for (int ks = 0; ks < 4; ks++) {
            const int kb = ks * 16;
            unsigned af[4][4];
#pragma unroll
            for (int mi = 0; mi < 4; mi++)
                ldmx4(af[mi][0], af[mi][1], af[mi][2], af[mi][3],
                      abase + (uint32_t)((wm + mi * 16 + a_row) * GSTR + kb + a_col) * 2u);
            unsigned bf[8][2];
#pragma unroll
            for (int ni2 = 0; ni2 < 4; ni2++)
                ldmx4(bf[2 * ni2][0], bf[2 * ni2][1], bf[2 * ni2 + 1][0], bf[2 * ni2 + 1][1],
                      bbase + (uint32_t)((wn + ni2 * 16 + b_row) * GSTR + kb + b_col) * 2u);
#pragma unroll
            for (int mi = 0; mi < 4; mi++)
#pragma unroll
                for (int ni = 0; ni < 8; ni++)
                    mma16(acc[mi][ni][0], acc[mi][ni][1], acc[mi][ni][2], acc[mi][ni][3],
                          af[mi][0], af[mi][1], af[mi][2], af[mi][3],
                          bf[ni][0], bf[ni][1]);
        }
    }

    // epilogue
#pragma unroll
    for (int mi = 0; mi < 4; mi++)
#pragma unroll
        for (int ni = 0; ni < 8; ni++)
#pragma unroll
            for (int eh = 0; eh < 2; eh++) {
                const int gr = row0 + wm + mi * 16 + lr + (eh << 3);
                const int gc = col0 + wn + ni * 8 + (lc << 1);
                float v0 = acc[mi][ni][eh * 2]     + __ldg(bias + gc);
                float v1 = acc[mi][ni][eh * 2 + 1] + __ldg(bias + gc + 1);
                if (mode == 2) {
                    float* dst = (float*)dstp;
                    *reinterpret_cast<float2*>(dst + (size_t)gr * DM + gc) =
                        make_float2(v0, v1);
                } else {
                    if (mode == 0) { v0 *= 0.125f; v1 *= 0.125f; }
                    __half* dst = (__half*)dstp;
                    const int tb = gr >> 10, n = gr & 1023;
                    const int h = gc >> 6, d = gc & 63;
                    __half2 hv = __floats2half2_rn(v0, v1);
                    *reinterpret_cast<__half2*>(
                        dst + (((size_t)(tb * NH + h)) * NSEQ + n) * DHD + d) = hv;
                }
            }
}

__global__ __launch_bounds__(128) void gemm_qkv_k(const float* __restrict__ bq,
                                                  const float* __restrict__ bk,
                                                  const float* __restrict__ bv) {
    const int z = blockIdx.z;
    const __half* W = (z == 0) ? g_wqc : (z == 1) ? g_wkc : g_wvc;
    const float* b = (z == 0) ? bq : (z == 1) ? bk : bv;
    __half* dst = (z == 0) ? g_q : (z == 1) ? g_k : g_v;
    gemm_body(g_xc, W, b, dst, (z == 0) ? 0 : 1);
}

__global__ __launch_bounds__(128) void gemm_out_k(const float* __restrict__ bo,
                                                  float* __restrict__ out) {
    gemm_body(g_ctx, g_woc, bo, out, 2);
}

// ---------------------------------------------------------------------------
// Attention (fp16): per (tb,h), 1024x1024x64. CTA = 128 q-rows, 128 threads,
// KV block 32, 2-stage cp.async, 2 CTAs/SM.
// S-phase frags via ldmatrix.x4; P stays IN REGISTERS (the S-accumulator
// fragment layout IS the P@V A-fragment layout) -> no P smem roundtrip.
// V B-frags via ldmatrix.x4.trans.
// ---------------------------------------------------------------------------
#define ASTR 72                      // Q/K/V row stride in halves (144 B)
#define AQ_H   (128 * ASTR)          // 9216
#define AK_H   (32 * ASTR)           // 2304
#define AV_H   (32 * ASTR)           // 2304
#define ATT_SMEM_B ((AQ_H + 2 * AK_H + 2 * AV_H) * 2)   // 36864 B

__global__ __launch_bounds__(128, 2) void attn_k() {
    extern __shared__ __half smh[];
    const uint32_t smb = smem_u32(smh);

    const int tid = threadIdx.x, lane = tid & 31, wid = tid >> 5;
    const int lr = lane >> 2, lc = lane & 3;
    const int qb = blockIdx.x, tbh = blockIdx.y;
    const __half* qp = g_q + (size_t)tbh * NSEQ * DHD + (size_t)qb * 128 * DHD;
    const __half* kp = g_k + (size_t)tbh * NSEQ * DHD;
    const __half* vp = g_v + (size_t)tbh * NSEQ * DHD;

    const int m8 = lane >> 3, rr = lane & 7;
    const int a_row = ((m8 & 1) << 3) + rr;
    const int a_col = (m8 >> 1) << 3;
    const int b_row = ((m8 >> 1) << 3) + rr;
    const int b_col = (m8 & 1) << 3;

    // prefetch KV stage: K 256 + V 256 chunks of 16B, 2+2 per thread
    auto prefetch_kv = [&](int s, int kvb) {
        const uint32_t kb = smb + (uint32_t)(AQ_H + s * AK_H) * 2u;
        const uint32_t vb = smb + (uint32_t)(AQ_H + 2 * AK_H + s * AV_H) * 2u;
        const __half* kg = kp + (size_t)kvb * 32 * DHD;
        const __half* vg = vp + (size_t)kvb * 32 * DHD;
#pragma unroll
        for (int u = tid; u < 256; u += 128) {
            const int row = u >> 3, c = (u & 7) << 3;
            cp16(kb + (uint32_t)(row * ASTR + c) * 2u, kg + row * DHD + c);
        }
#pragma unroll
        for (int u = tid; u < 256; u += 128) {
            const int row = u >> 3, c = (u & 7) << 3;
            cp16(vb + (uint32_t)(row * ASTR + c) * 2u, vg + row * DHD + c);
        }
    };

    // Q load (once, 128x64 halves = 1024 chunks) + first KV stage
#pragma unroll
    for (int u = tid; u < 1024; u += 128) {
        const int row = u >> 3, c = (u & 7) << 3;
        cp16(smb + (uint32_t)(row * ASTR + c) * 2u, qp + row * DHD + c);
    }
    prefetch_kv(0, 0);
    CP_COMMIT();

    float ctx[2][8][4];
#pragma unroll
    for (int i = 0; i < 2; i++)
#pragma unroll
        for (int j = 0; j < 8; j++)
#pragma unroll
            for (int e = 0; e < 4; e++) ctx[i][j][e] = 0.f;
    float rs[2][2] = {{0.f, 0.f}, {0.f, 0.f}};

    const int wm = wid * 32;
    const uint32_t kstage[2] = {
        smb + (uint32_t)AQ_H * 2u,
        smb + (uint32_t)(AQ_H + AK_H) * 2u
    };
    const uint32_t vstage[2] = {
        smb + (uint32_t)(AQ_H + 2 * AK_H) * 2u,
        smb + (uint32_t)(AQ_H + 2 * AK_H + AV_H) * 2u
    };

    for (int kvb = 0; kvb < NSEQ / 32; kvb++) {
        const int s = kvb & 1;
        if (kvb + 1 < NSEQ / 32) {
            prefetch_kv(s ^ 1, kvb + 1);
            CP_COMMIT();
            CP_WAIT(1);
        } else {
            CP_WAIT(0);
        }
        __syncthreads();

        // S = q_s @ k^T (warp: 32 q-rows x 32 keys), k-dim = dh 64 = 4 x k16
        float sacc[2][4][4];
#pragma unroll
        for (int i = 0; i < 2; i++)
#pragma unroll
            for (int j = 0; j < 4; j++)
#pragma unroll
                for (int e = 0; e < 4; e++) sacc[i][j][e] = 0.f;

#pragma unroll
        for (int ks = 0; ks < 4; ks++) {
            const int kb = ks * 16;
            unsigned af[2][4];
#pragma unroll
            for (int mi = 0; mi < 2; mi++)
                ldmx4(af[mi][0], af[mi][1], af[mi][2], af[mi][3],
                      smb + (uint32_t)((wm + mi * 16 + a_row) * ASTR + kb + a_col) * 2u);
            unsigned bf[4][2];
#pragma unroll
            for (int ni2 = 0; ni2 < 2; ni2++)
                ldmx4(bf[2 * ni2][0], bf[2 * ni2][1], bf[2 * ni2 + 1][0], bf[2 * ni2 + 1][1],
                      kstage[s] + (uint32_t)((ni2 * 16 + b_row) * ASTR + kb + b_col) * 2u);
#pragma unroll
            for (int mi = 0; mi < 2; mi++)
#pragma unroll
                for (int ni = 0; ni < 4; ni++)
                    mma16(sacc[mi][ni][0], sacc[mi][ni][1], sacc[mi][ni][2], sacc[mi][ni][3],
                          af[mi][0], af[mi][1], af[mi][2], af[mi][3],
                          bf[ni][0], bf[ni][1]);
        }

        // relu in place + rowsum (fp32)
#pragma unroll
        for (int mi = 0; mi < 2; mi++)
#pragma unroll
            for (int ni = 0; ni < 4; ni++) {
                float p0 = fmaxf(sacc[mi][ni][0], 0.f);
                float p1 = fmaxf(sacc[mi][ni][1], 0.f);
                float p2 = fmaxf(sacc[mi][ni][2], 0.f);
                float p3 = fmaxf(sacc[mi][ni][3], 0.f);
                sacc[mi][ni][0] = p0; sacc[mi][ni][1] = p1;
                sacc[mi][ni][2] = p2; sacc[mi][ni][3] = p3;
                rs[mi][0] += p0 + p1;
                rs[mi][1] += p2 + p3;
            }

        // ctx += P @ V ; P fragments built from sacc registers (layout match):
        // af[mi][0] = P[row lr      ][k 2lc..] = sacc[mi][2ks][0..1]
        // af[mi][1] = P[row lr+8    ][k 2lc..] = sacc[mi][2ks][2..3]
        // af[mi][2] = P[row lr      ][k 2lc+8] = sacc[mi][2ks+1][0..1]
        // af[mi][3] = P[row lr+8    ][k 2lc+8] = sacc[mi][2ks+1][2..3]
#pragma unroll
        for (int ks = 0; ks < 2; ks++) {
            unsigned af[2][4];
#pragma unroll
            for (int mi = 0; mi < 2; mi++) {
                af[mi][0] = packh2(sacc[mi][2 * ks][0],     sacc[mi][2 * ks][1]);
                af[mi][1] = packh2(sacc[mi][2 * ks][2],     sacc[mi][2 * ks][3]);
                af[mi][2] = packh2(sacc[mi][2 * ks + 1][0], sacc[mi][2 * ks + 1][1]);
                af[mi][3] = packh2(sacc[mi][2 * ks + 1][2], sacc[mi][2 * ks + 1][3]);
            }
            unsigned bf[8][2];
            const int vkey = ks * 16 + (lane & 15);
            const int vcol8 = (lane >> 4) << 3;
#pragma unroll
            for (int ni2 = 0; ni2 < 4; ni2++) {
                const uint32_t addr = vstage[s] +
                    (uint32_t)(vkey * ASTR + ni2 * 16 + vcol8) * 2u;
                ldmx4t(bf[2 * ni2][0], bf[2 * ni2][1],
                       bf[2 * ni2 + 1][0], bf[2 * ni2 + 1][1], addr);
            }
#pragma unroll
            for (int mi = 0; mi < 2; mi++)
#pragma unroll
                for (int ni = 0; ni < 8; ni++)
                    mma16(ctx[mi][ni][0], ctx[mi][ni][1], ctx[mi][ni][2], ctx[mi][ni][3],
                          af[mi][0], af[mi][1], af[mi][2], af[mi][3],
                          bf[ni][0], bf[ni][1]);
        }
        __syncthreads();
    }

    // finalize rowsums (reduce across the 4 lanes sharing a row)
    float inv[2][2];
#pragma unroll
    for (int mi = 0; mi < 2; mi++)
#pragma unroll
        for (int hh = 0; hh < 2; hh++) {
            float r = rs[mi][hh];
            r += __shfl_xor_sync(0xffffffffu, r, 1);
            r += __shfl_xor_sync(0xffffffffu, r, 2);
            inv[mi][hh] = 1.f / (r + 1e-6f);
        }

    // write merged ctx [s, h*64+d] as fp16 (feeds out-proj GEMM)
    const int tb = tbh / NH, h = tbh % NH;
#pragma unroll
    for (int mi = 0; mi < 2; mi++)
#pragma unroll
        for (int ni = 0; ni < 8; ni++)
#pragma unroll
            for (int eh = 0; eh < 2; eh++) {
                const int qrow = qb * 128 + wm + mi * 16 + lr + (eh << 3);
                const int sidx = tb * NSEQ + qrow;
                const int c = h * DHD + ni * 8 + (lc << 1);
                const float iv = inv[mi][eh];
                *reinterpret_cast<__half2*>(&g_ctx[(size_t)sidx * DM + c]) =
                    __floats2half2_rn(ctx[mi][ni][eh * 2] * iv,
                                      ctx[mi][ni][eh * 2 + 1] * iv);
            }
}

// ---------------------------------------------------------------------------
// Launch
// ---------------------------------------------------------------------------
extern "C" void kernel_launch(void* const* d_in, const int* in_sizes, int n_in,
                              void* d_out, int out_size) {
    const float* x  = (const float*)d_in[0];
    const float* Wq = (const float*)d_in[1];
    const float* bq = (const float*)d_in[2];
    const float* Wk = (const float*)d_in[3];
    const float* bk = (const float*)d_in[4];
    const float* Wv = (const float*)d_in[5];
    const float* bv = (const float*)d_in[6];
    const float* Wo = (const float*)d_in[7];
    const float* bo = (const float*)d_in[8];
    float* out = (float*)d_out;

    (void)in_sizes; (void)n_in; (void)out_size;

    cudaFuncSetAttribute(gemm_qkv_k, cudaFuncAttributeMaxDynamicSharedMemorySize, GSMEM_B);
    cudaFuncSetAttribute(gemm_out_k, cudaFuncAttributeMaxDynamicSharedMemorySize, GSMEM_B);
    cudaFuncSetAttribute(attn_k, cudaFuncAttributeMaxDynamicSharedMemorySize, ATT_SMEM_B);

    // fused fp16 pre-convert (x + 4 weights, one launch)
    cvt_all_k<<<(NCVT4 + 255) / 256, 256>>>(x, Wq, Wk, Wv, Wo);

    // q/k/v projections (CTA 128x128, 4 warps of 64x64)
    gemm_qkv_k<<<dim3(NS / GBM, DM / GBN, 3), 128, GSMEM_B>>>(bq, bk, bv);

    // spike attention
    attn_k<<<dim3(NSEQ / 128, NTB * NH), 128, ATT_SMEM_B>>>();

    // output projection
    gemm_out_k<<<dim3(NS / GBM, DM / GBN), 128, GSMEM_B>>>(bo, out);
}